// round 16
// baseline (speedup 1.0000x reference)
#include <cuda_runtime.h>
#include <cuda_fp16.h>
#include <math.h>
#include <stdint.h>

#define BN 4
#define CN 64
#define HN 256
#define WN 256
#define NPIX (HN*WN)            // 65536
#define NOFF0 50
#define NOFFS 98

// ---------------- scratch (static device globals; no allocation) ----------------
__device__ __align__(1024) float g_xt[BN*NPIX*CN];       // x transposed to NHWC
__device__ __align__(1024) float g_hraw[BN*NPIX*CN];     // conv3x3 raw output, NHWC
__device__ __align__(1024) float g_t[BN*NPIX*CN];        // gelu(p1(norm(h))), NHWC
__device__ __align__(1024) float g_a[BN*NPIX*CN];        // deform5 output fp32, NHWC
__device__ __align__(1024) float g_a2[BN*NPIX*CN];       // deform7 output, NHWC
__device__ __align__(1024) __half g_th[BN*NPIX*CN];      // g_t in fp16 (offset-conv A)
__device__ __align__(1024) __half g_ah[BN*NPIX*CN];      // g_a in fp16 (offset-conv A)
__device__ __align__(1024) float g_off0[BN*NPIX*NOFF0];  // 5x5 offsets, NHWC(50)
__device__ __align__(1024) float g_offs[BN*NPIX*NOFFS];  // 7x7 offsets, NHWC(98)
__device__ __align__(1024) __half g_wTh[49*112*64];      // 7x7 weights [t][n][k], fp16
__device__ __align__(1024) __half g_wT0h[25*64*64];      // 5x5 weights [t][n][k], fp16
__device__ __align__(1024) __half g_w3hh[9*64*64];       // 3x3 weights hi, fp16
__device__ __align__(1024) __half g_w3ll[9*64*64];       // 3x3 weights lo, fp16
__device__ __align__(1024) __half g_p1hh[64*64], g_p1ll[64*64];  // p1 weights hi/lo
__device__ __align__(1024) __half g_g1hh[64*64], g_g1ll[64*64];  // g1 weights hi/lo
__device__ __align__(1024) __half g_p2hh[64*64], g_p2ll[64*64];  // p2 weights hi/lo
__device__ float g_partial[2048*128];                    // per-CTA (sum,sumsq)/channel
__device__ float g_stats[BN*CN*2];                       // mean, rstd per (b,c)

// ---------------- helpers ----------------
__device__ __forceinline__ void mma_f16(float* c, const uint32_t* a, uint32_t b0, uint32_t b1) {
    asm volatile("mma.sync.aligned.m16n8k16.row.col.f32.f16.f16.f32 "
        "{%0,%1,%2,%3}, {%4,%5,%6,%7}, {%8,%9}, {%0,%1,%2,%3};"
        : "+f"(c[0]), "+f"(c[1]), "+f"(c[2]), "+f"(c[3])
        : "r"(a[0]), "r"(a[1]), "r"(a[2]), "r"(a[3]), "r"(b0), "r"(b1));
}
__device__ __forceinline__ float gelu_f(float v) {
    return 0.5f*v*(1.f + erff(v*0.70710678118654752f));
}
__device__ __forceinline__ uint32_t smem_u32(const void* p) {
    uint32_t a;
    asm("{ .reg .u64 t; cvta.to.shared.u64 t, %1; cvt.u32.u64 %0, t; }" : "=r"(a) : "l"(p));
    return a;
}
__device__ __forceinline__ void ldsm_x4(uint32_t& r0, uint32_t& r1, uint32_t& r2, uint32_t& r3,
                                        uint32_t addr) {
    asm volatile("ldmatrix.sync.aligned.m8n8.x4.shared.b16 {%0,%1,%2,%3}, [%4];"
        : "=r"(r0), "=r"(r1), "=r"(r2), "=r"(r3) : "r"(addr));
}
__device__ __forceinline__ void ldsm_x2(uint32_t& r0, uint32_t& r1, uint32_t addr) {
    asm volatile("ldmatrix.sync.aligned.m8n8.x2.shared.b16 {%0,%1}, [%2];"
        : "=r"(r0), "=r"(r1) : "r"(addr));
}

// ---------------- K0: repack weights ----------------
__global__ __launch_bounds__(256) void k_repack(const float* __restrict__ offs_w,
                                                const float* __restrict__ off0_w,
                                                const float* __restrict__ conv_w,
                                                const float* __restrict__ p1w,
                                                const float* __restrict__ g1w,
                                                const float* __restrict__ p2w)
{
    int i = blockIdx.x*256 + threadIdx.x;
    if (i < 49*112*64) {
        int t = i/(112*64); int rem = i%(112*64); int n = rem >> 6; int k = rem & 63;
        float v = (n < 98) ? offs_w[(n*64 + k)*49 + t] : 0.f;
        g_wTh[i] = __float2half_rn(v);
    }
    if (i < 25*64*64) {
        int t = i >> 12; int n = (i >> 6) & 63; int k = i & 63;
        float v = (n < 50) ? off0_w[(n*64 + k)*25 + t] : 0.f;
        g_wT0h[i] = __float2half_rn(v);
    }
    if (i < 9*64*64) {
        int t = i >> 12; int n = (i >> 6) & 63; int k = i & 63;
        float v = conv_w[(n*64 + k)*9 + t];
        __half h = __float2half_rn(v);
        g_w3hh[i] = h;
        g_w3ll[i] = __float2half_rn(v - __half2float(h));
    }
    if (i < 64*64) {
        float v1 = p1w[i];
        __half h1 = __float2half_rn(v1);
        g_p1hh[i] = h1; g_p1ll[i] = __float2half_rn(v1 - __half2float(h1));
        float v2 = g1w[i];
        __half h2 = __float2half_rn(v2);
        g_g1hh[i] = h2; g_g1ll[i] = __float2half_rn(v2 - __half2float(h2));
        float v3 = p2w[i];
        __half h3 = __float2half_rn(v3);
        g_p2hh[i] = h3; g_p2ll[i] = __float2half_rn(v3 - __half2float(h3));
    }
}

// ---------------- K1a: transpose x NCHW -> NHWC ----------------
__global__ __launch_bounds__(256) void k_nchw2nhwc(const float* __restrict__ x)
{
    __shared__ float sm[64*33];
    int b = blockIdx.y;
    int pix0 = blockIdx.x*32;
#pragma unroll
    for (int i = 0; i < 8; i++) {
        int idx = threadIdx.x + i*256;
        int c = idx >> 5, p = idx & 31;
        sm[c*33 + p] = x[((size_t)(b*64 + c) << 16) + pix0 + p];
    }
    __syncthreads();
#pragma unroll
    for (int i = 0; i < 8; i++) {
        int idx = threadIdx.x + i*256;
        int p = idx >> 6, c = idx & 63;
        g_xt[(((size_t)b << 16) + pix0 + p)*64 + c] = sm[c*33 + p];
    }
}

// ---------------- K1b: conv3x3 via split-fp16 mma (ldmatrix frags) + fused stats ----------------
__global__ __launch_bounds__(256) void k_conv3x3_mma(float* __restrict__ outp)
{
    extern __shared__ char sraw[];
    __half* Ah = (__half*)sraw;        // [128][72]
    __half* Al = Ah + 128*72;
    __half* Bh = Al + 128*72;          // [64][72]
    __half* Bl = Bh + 64*72;
    __shared__ float sred_s[4][64], sred_q[4][64];
    const int tid = threadIdx.x;
    const int wid = tid >> 5, lane = tid & 31;
    const int grp = lane >> 2, tig = lane & 3;
    const int jj = lane >> 3, li = lane & 7;
    const int wm = wid & 3, wn = wid >> 2;
    const int x0 = blockIdx.x*16, y0 = blockIdx.y*8, b = blockIdx.z;

    const uint32_t aHb = smem_u32(Ah) + (((wm*32 + (jj&1)*8 + li)*72 + (jj>>1)*8) << 1);
    const uint32_t aLb = smem_u32(Al) + (((wm*32 + (jj&1)*8 + li)*72 + (jj>>1)*8) << 1);
    const uint32_t bHb = smem_u32(Bh) + (((wn*32 + (jj>>1)*8 + li)*72 + (jj&1)*8) << 1);
    const uint32_t bLb = smem_u32(Bl) + (((wn*32 + (jj>>1)*8 + li)*72 + (jj&1)*8) << 1);

    float c[2][4][4];
#pragma unroll
    for (int mi = 0; mi < 2; mi++)
#pragma unroll
        for (int ni = 0; ni < 4; ni++)
#pragma unroll
            for (int j = 0; j < 4; j++) c[mi][ni][j] = 0.f;

    for (int t = 0; t < 9; t++) {
        int dy = t/3 - 1, dx = t%3 - 1;
#pragma unroll
        for (int i = 0; i < 4; i++) {
            int idx = tid + i*256;
            int p = idx >> 3, f8 = idx & 7;
            int gy = y0 + (p >> 4) + dy, gx = x0 + (p & 15) + dx;
            float4 v0 = make_float4(0.f,0.f,0.f,0.f), v1 = v0;
            if ((unsigned)gy < 256u && (unsigned)gx < 256u) {
                const float* s = g_xt + ((((size_t)b << 16) + (gy << 8) + gx) << 6) + f8*8;
                v0 = *(const float4*)s;
                v1 = *(const float4*)(s + 4);
            }
            float vf[8] = {v0.x, v0.y, v0.z, v0.w, v1.x, v1.y, v1.z, v1.w};
            __half hh[8], ll[8];
#pragma unroll
            for (int e = 0; e < 8; e++) {
                hh[e] = __float2half_rn(vf[e]);
                ll[e] = __float2half_rn(vf[e] - __half2float(hh[e]));
            }
            *(uint4*)(Ah + p*72 + f8*8) = *(uint4*)hh;
            *(uint4*)(Al + p*72 + f8*8) = *(uint4*)ll;
        }
#pragma unroll
        for (int i = 0; i < 2; i++) {
            int idx = tid + i*256;
            int n = idx >> 3, f8 = idx & 7;
            *(uint4*)(Bh + n*72 + f8*8) = *(const uint4*)(g_w3hh + ((size_t)t*64 + n)*64 + f8*8);
            *(uint4*)(Bl + n*72 + f8*8) = *(const uint4*)(g_w3ll + ((size_t)t*64 + n)*64 + f8*8);
        }
        __syncthreads();
#pragma unroll
        for (int kc = 0; kc < 4; kc++) {
            uint32_t aH[2][4], aL[2][4], bH[4][2], bL[4][2];
            ldsm_x4(aH[0][0], aH[0][1], aH[0][2], aH[0][3], aHb + kc*32);
            ldsm_x4(aH[1][0], aH[1][1], aH[1][2], aH[1][3], aHb + 2304 + kc*32);
            ldsm_x4(aL[0][0], aL[0][1], aL[0][2], aL[0][3], aLb + kc*32);
            ldsm_x4(aL[1][0], aL[1][1], aL[1][2], aL[1][3], aLb + 2304 + kc*32);
            ldsm_x4(bH[0][0], bH[0][1], bH[1][0], bH[1][1], bHb + kc*32);
            ldsm_x4(bH[2][0], bH[2][1], bH[3][0], bH[3][1], bHb + 2304 + kc*32);
            ldsm_x4(bL[0][0], bL[0][1], bL[1][0], bL[1][1], bLb + kc*32);
            ldsm_x4(bL[2][0], bL[2][1], bL[3][0], bL[3][1], bLb + 2304 + kc*32);
#pragma unroll
            for (int ni = 0; ni < 4; ni++) {
                mma_f16(c[0][ni], aH[0], bH[ni][0], bH[ni][1]);
                mma_f16(c[1][ni], aH[1], bH[ni][0], bH[ni][1]);
                mma_f16(c[0][ni], aL[0], bH[ni][0], bH[ni][1]);
                mma_f16(c[1][ni], aL[1], bH[ni][0], bH[ni][1]);
                mma_f16(c[0][ni], aH[0], bL[ni][0], bL[ni][1]);
                mma_f16(c[1][ni], aH[1], bL[ni][0], bL[ni][1]);
            }
        }
        __syncthreads();
    }
#pragma unroll
    for (int mi = 0; mi < 2; mi++) {
        int p0 = wm*32 + mi*16 + grp;
        int yA = y0 + (p0 >> 4),        xA = x0 + (p0 & 15);
        int yB = y0 + ((p0 + 8) >> 4),  xB = x0 + ((p0 + 8) & 15);
        float* ptr0 = outp + ((((size_t)b << 16) + (yA << 8) + xA) << 6);
        float* ptr1 = outp + ((((size_t)b << 16) + (yB << 8) + xB) << 6);
#pragma unroll
        for (int ni = 0; ni < 4; ni++) {
            int cn = wn*32 + ni*8 + 2*tig;
            *(float2*)(ptr0 + cn) = make_float2(c[mi][ni][0], c[mi][ni][1]);
            *(float2*)(ptr1 + cn) = make_float2(c[mi][ni][2], c[mi][ni][3]);
        }
    }
    // fused instance-norm partials
#pragma unroll
    for (int ni = 0; ni < 4; ni++) {
        float s0 = c[0][ni][0] + c[1][ni][0] + c[0][ni][2] + c[1][ni][2];
        float q0 = c[0][ni][0]*c[0][ni][0] + c[1][ni][0]*c[1][ni][0]
                 + c[0][ni][2]*c[0][ni][2] + c[1][ni][2]*c[1][ni][2];
        float s1 = c[0][ni][1] + c[1][ni][1] + c[0][ni][3] + c[1][ni][3];
        float q1 = c[0][ni][1]*c[0][ni][1] + c[1][ni][1]*c[1][ni][1]
                 + c[0][ni][3]*c[0][ni][3] + c[1][ni][3]*c[1][ni][3];
#pragma unroll
        for (int d = 16; d >= 4; d >>= 1) {
            s0 += __shfl_down_sync(0xffffffffu, s0, d);
            q0 += __shfl_down_sync(0xffffffffu, q0, d);
            s1 += __shfl_down_sync(0xffffffffu, s1, d);
            q1 += __shfl_down_sync(0xffffffffu, q1, d);
        }
        if (grp == 0) {
            int cn = wn*32 + ni*8 + 2*tig;
            sred_s[wm][cn] = s0; sred_q[wm][cn] = q0;
            sred_s[wm][cn+1] = s1; sred_q[wm][cn+1] = q1;
        }
    }
    __syncthreads();
    if (tid < 64) {
        float S = sred_s[0][tid] + sred_s[1][tid] + sred_s[2][tid] + sred_s[3][tid];
        float Q = sred_q[0][tid] + sred_q[1][tid] + sred_q[2][tid] + sred_q[3][tid];
        int blk = b*512 + blockIdx.y*16 + blockIdx.x;
        g_partial[blk*128 + tid*2    ] = S;
        g_partial[blk*128 + tid*2 + 1] = Q;
    }
}

// ---------------- K2: stats final ----------------
__global__ __launch_bounds__(64) void k_stats_final2()
{
    int bc = blockIdx.x;
    int b = bc >> 6, c = bc & 63;
    int tid = threadIdx.x;
    float s = 0.f, q = 0.f;
    for (int i = tid; i < 512; i += 64) {
        s += g_partial[(b*512 + i)*128 + c*2];
        q += g_partial[(b*512 + i)*128 + c*2 + 1];
    }
    __shared__ float sh[4];
#pragma unroll
    for (int d = 16; d; d >>= 1) {
        s += __shfl_down_sync(0xffffffffu, s, d);
        q += __shfl_down_sync(0xffffffffu, q, d);
    }
    if ((tid & 31) == 0) { sh[(tid>>5)*2] = s; sh[(tid>>5)*2 + 1] = q; }
    __syncthreads();
    if (tid == 0) {
        float S = sh[0] + sh[2], Q = sh[1] + sh[3];
        float m = S * (1.f/65536.f);
        float var = Q * (1.f/65536.f) - m*m;
        g_stats[bc*2    ] = m;
        g_stats[bc*2 + 1] = rsqrtf(var + 1e-5f);
    }
}

// ---------------- K3: t = gelu(p1 @ norm(h) + b) via split-fp16 mma ----------------
__global__ __launch_bounds__(256) void k_p1_mma(const float* __restrict__ p1b)
{
    extern __shared__ char sraw[];
    __half* Ah = (__half*)sraw;        // [128][72]
    __half* Al = Ah + 128*72;
    __half* Bh = Al + 128*72;          // [64][72]
    __half* Bl = Bh + 64*72;
    __shared__ float mS[64], rS[64];
    const int tid = threadIdx.x;
    const int wid = tid >> 5, lane = tid & 31;
    const int grp = lane >> 2, tig = lane & 3;
    const int wm = wid & 3, wn = wid >> 2;
    const int b = blockIdx.y;
    const int pix0 = blockIdx.x*128;
    if (tid < 64) {
        mS[tid] = g_stats[(b*64 + tid)*2];
        rS[tid] = g_stats[(b*64 + tid)*2 + 1];
    }
    __syncthreads();
#pragma unroll
    for (int i = 0; i < 2; i++) {
        int idx = tid + i*256;
        int n = idx >> 3, f8 = idx & 7;
        *(uint4*)(Bh + n*72 + f8*8) = *(const uint4*)(g_p1hh + n*64 + f8*8);
        *(uint4*)(Bl + n*72 + f8*8) = *(const uint4*)(g_p1ll + n*64 + f8*8);
    }
    const float* src = g_hraw + ((size_t)b*NPIX + pix0)*64;
#pragma unroll
    for (int i = 0; i < 4; i++) {
        int idx = tid + i*256;
        int p = idx >> 3, f8 = idx & 7;
        const float* s = src + (size_t)p*64 + f8*8;
        float4 v0 = *(const float4*)s, v1 = *(const float4*)(s + 4);
        float vf[8] = {v0.x, v0.y, v0.z, v0.w, v1.x, v1.y, v1.z, v1.w};
        __half hh[8], ll[8];
        int c0 = f8*8;
#pragma unroll
        for (int e = 0; e < 8; e++) {
            float nv = (vf[e] - mS[c0 + e])*rS[c0 + e];
            hh[e] = __float2half_rn(nv);
            ll[e] = __float2half_rn(nv - __half2float(hh[e]));
        }
        *(uint4*)(Ah + p*72 + f8*8) = *(uint4*)hh;
        *(uint4*)(Al + p*72 + f8*8) = *(uint4*)ll;
    }
    __syncthreads();
    float c[2][4][4];
#pragma unroll
    for (int mi = 0; mi < 2; mi++)
#pragma unroll
        for (int ni = 0; ni < 4; ni++)
#pragma unroll
            for (int j = 0; j < 4; j++) c[mi][ni][j] = 0.f;
    const uint32_t* AuH = (const uint32_t*)Ah;
    const uint32_t* AuL = (const uint32_t*)Al;
    const uint32_t* BuH = (const uint32_t*)Bh;
    const uint32_t* BuL = (const uint32_t*)Bl;
#pragma unroll
    for (int kc = 0; kc < 4; kc++) {
        int k0 = kc*8;
        uint32_t aH[2][4], aL[2][4];
#pragma unroll
        for (int mi = 0; mi < 2; mi++) {
            int r = wm*32 + mi*16;
            aH[mi][0] = AuH[(r + grp    )*36 + k0 + tig];
            aH[mi][1] = AuH[(r + grp + 8)*36 + k0 + tig];
            aH[mi][2] = AuH[(r + grp    )*36 + k0 + tig + 4];
            aH[mi][3] = AuH[(r + grp + 8)*36 + k0 + tig + 4];
            aL[mi][0] = AuL[(r + grp    )*36 + k0 + tig];
            aL[mi][1] = AuL[(r + grp + 8)*36 + k0 + tig];
            aL[mi][2] = AuL[(r + grp    )*36 + k0 + tig + 4];
            aL[mi][3] = AuL[(r + grp + 8)*36 + k0 + tig + 4];
        }
#pragma unroll
        for (int ni = 0; ni < 4; ni++) {
            int cn = wn*32 + ni*8;
            uint32_t bh0 = BuH[(cn + grp)*36 + k0 + tig];
            uint32_t bh1 = BuH[(cn + grp)*36 + k0 + tig + 4];
            uint32_t bl0 = BuL[(cn + grp)*36 + k0 + tig];
            uint32_t bl1 = BuL[(cn + grp)*36 + k0 + tig + 4];
            mma_f16(c[0][ni], aH[0], bh0, bh1);
            mma_f16(c[1][ni], aH[1], bh0, bh1);
            mma_f16(c[0][ni], aL[0], bh0, bh1);
            mma_f16(c[1][ni], aL[1], bh0, bh1);
            mma_f16(c[0][ni], aH[0], bl0, bl1);
            mma_f16(c[1][ni], aH[1], bl0, bl1);
        }
    }
#pragma unroll
    for (int mi = 0; mi < 2; mi++) {
        int p0 = wm*32 + mi*16 + grp;
        size_t base0 = ((size_t)b*NPIX + pix0 + p0)*64;
        size_t base1 = ((size_t)b*NPIX + pix0 + p0 + 8)*64;
#pragma unroll
        for (int ni = 0; ni < 4; ni++) {
            int cn = wn*32 + ni*8 + 2*tig;
            float b0 = __ldg(p1b + cn), b1 = __ldg(p1b + cn + 1);
            float r0 = gelu_f(c[mi][ni][0] + b0);
            float r1 = gelu_f(c[mi][ni][1] + b1);
            float r2 = gelu_f(c[mi][ni][2] + b0);
            float r3 = gelu_f(c[mi][ni][3] + b1);
            *(float2*)(g_t + base0 + cn) = make_float2(r0, r1);
            *(float2*)(g_t + base1 + cn) = make_float2(r2, r3);
            __half2 h01 = __floats2half2_rn(r0, r1);
            __half2 h23 = __floats2half2_rn(r2, r3);
            *(uint32_t*)(g_th + base0 + cn) = *(uint32_t*)&h01;
            *(uint32_t*)(g_th + base1 + cn) = *(uint32_t*)&h23;
        }
    }
}

// ---------------- implicit-GEMM offset conv: fp16 mma + ldmatrix + smem double buffer ----------------
template<int COUT, int NPAD, int NT, int KW, int DIL, int PAD>
__global__ __launch_bounds__(256) void k_conv_mma_h(const __half* __restrict__ src,
                                                    const __half* __restrict__ wT,
                                                    const float* __restrict__ bias,
                                                    float* __restrict__ outp)
{
    constexpr int NWN = NPAD/2;
    constexpr int NTILE = NWN/8;
    constexpr int BCH = NPAD*8;
    constexpr int BUF = (128 + NPAD)*72;
    extern __shared__ char sraw[];
    __half* As[2] = { (__half*)sraw, (__half*)sraw + BUF };
    __half* Bs[2] = { As[0] + 128*72, As[1] + 128*72 };
    const int tid = threadIdx.x;
    const int wid = tid >> 5, lane = tid & 31;
    const int grp = lane >> 2, tig = lane & 3;
    const int jj = lane >> 3, li = lane & 7;
    const int wm = wid & 3, wn = wid >> 2;
    const int x0 = blockIdx.x*16, y0 = blockIdx.y*8, b = blockIdx.z;

    uint32_t aB[2], bB[2], bB2[2];
#pragma unroll
    for (int d = 0; d < 2; d++) {
        aB[d]  = smem_u32(As[d]) + (((wm*32 + (jj&1)*8 + li)*72 + (jj>>1)*8) << 1);
        bB[d]  = smem_u32(Bs[d]) + (((wn*NWN + (jj>>1)*8 + li)*72 + (jj&1)*8) << 1);
        bB2[d] = smem_u32(Bs[d]) + (((wn*NWN + (NTILE-1)*8 + li)*72 + ((lane>>3)&1)*8) << 1);
    }

    float c[2][NTILE][4];
#pragma unroll
    for (int mi = 0; mi < 2; mi++)
#pragma unroll
        for (int ni = 0; ni < NTILE; ni++)
#pragma unroll
            for (int j = 0; j < 4; j++) c[mi][ni][j] = 0.f;

    auto stage = [&](int t, int d) {
        int dy = DIL*(t/KW) - PAD, dx = DIL*(t%KW) - PAD;
#pragma unroll
        for (int i = 0; i < 4; i++) {
            int idx = tid + i*256;
            int p = idx >> 3, f8 = idx & 7;
            int gy = y0 + (p >> 4) + dy, gx = x0 + (p & 15) + dx;
            uint4 v = make_uint4(0u, 0u, 0u, 0u);
            if ((unsigned)gy < 256u && (unsigned)gx < 256u)
                v = *(const uint4*)(src + ((((size_t)b << 16) + (gy << 8) + gx) << 6) + f8*8);
            *(uint4*)(As[d] + p*72 + f8*8) = v;
        }
#pragma unroll
        for (int i = 0; i < (BCH + 255)/256; i++) {
            int idx = tid + i*256;
            if (idx < BCH) {
                int n = idx >> 3, f8 = idx & 7;
                *(uint4*)(Bs[d] + n*72 + f8*8) =
                    *(const uint4*)(wT + ((size_t)t*NPAD + n)*64 + f8*8);
            }
        }
    };

    stage(0, 0);
    __syncthreads();
    for (int t = 0; t < NT; t++) {
        const int d = t & 1;
#pragma unroll
        for (int kc = 0; kc < 4; kc++) {
            uint32_t a[2][4], bf[NTILE][2];
            ldsm_x4(a[0][0], a[0][1], a[0][2], a[0][3], aB[d] + kc*32);
            ldsm_x4(a[1][0], a[1][1], a[1][2], a[1][3], aB[d] + 2304 + kc*32);
#pragma unroll
            for (int np = 0; np < NTILE/2; np++)
                ldsm_x4(bf[2*np][0], bf[2*np][1], bf[2*np+1][0], bf[2*np+1][1],
                        bB[d] + np*2304 + kc*32);
            if constexpr (NTILE & 1)
                ldsm_x2(bf[NTILE-1][0], bf[NTILE-1][1], bB2[d] + kc*32);
#pragma unroll
            for (int ni = 0; ni < NTILE; ni++) {
                mma_f16(c[0][ni], a[0], bf[ni][0], bf[ni][1]);
                mma_f16(c[1][ni], a[1], bf[ni][0], bf[ni][1]);
            }
        }
        if (t + 1 < NT) stage(t + 1, 1 - d);
        __syncthreads();
    }
#pragma unroll
    for (int mi = 0; mi < 2; mi++) {
        int p0 = wm*32 + mi*16 + grp;
        int yA = y0 + (p0 >> 4),        xA = x0 + (p0 & 15);
        int yB = y0 + ((p0 + 8) >> 4),  xB = x0 + ((p0 + 8) & 15);
        float* ptr0 = outp + (((size_t)b << 16) + (yA << 8) + xA)*COUT;
        float* ptr1 = outp + (((size_t)b << 16) + (yB << 8) + xB)*COUT;
#pragma unroll
        for (int ni = 0; ni < NTILE; ni++) {
            int cn = wn*NWN + ni*8 + 2*tig;
            if (cn < COUT) {
                float b0 = bias[cn], b1 = bias[cn+1];
                *(float2*)(ptr0 + cn) = make_float2(c[mi][ni][0] + b0, c[mi][ni][1] + b1);
                *(float2*)(ptr1 + cn) = make_float2(c[mi][ni][2] + b0, c[mi][ni][3] + b1);
            }
        }
    }
}

// ---------------- K5: deformable depthwise 5x5 (two-phase) ----------------
__global__ __launch_bounds__(256) void k_deform5(const float* __restrict__ dw)
{
    int b = blockIdx.y;
    int pix0 = blockIdx.x*16;
    int g = threadIdx.x >> 4;
    int c4 = (threadIdx.x & 15)*4;
    __shared__ float offS[16*NOFF0];
    __shared__ float wS[25*64];
    __shared__ float wPre[16*25*4];
    __shared__ int   aPre[16*25*4];
    for (int i = threadIdx.x; i < 16*NOFF0; i += 256)
        offS[i] = g_off0[((size_t)b*NPIX + pix0)*NOFF0 + i];
    for (int i = threadIdx.x; i < 25*64; i += 256) {
        int k = i >> 6, c = i & 63;
        wS[i] = dw[c*25 + k];
    }
    __syncthreads();
    for (int i = threadIdx.x; i < 16*25; i += 256) {
        int gg = i/25, k = i - gg*25;
        int pix = pix0 + gg;
        int y = pix >> 8, x = pix & 255;
        int ki = k/5, kj = k%5;
        float py = (float)(y - 2 + ki) + offS[gg*NOFF0 + 2*k];
        float px = (float)(x - 2 + kj) + offS[gg*NOFF0 + 2*k + 1];
        float y0f = floorf(py), x0f = floorf(px);
        float fy = py - y0f, fx = px - x0f;
        float wy0 = 1.f - fy, wx0 = 1.f - fx;
        int yi = (int)y0f, xi = (int)x0f;
        bool vy0 = (yi >= 0) && (yi <= 255);
        bool vy1 = (yi + 1 >= 0) && (yi + 1 <= 255);
        bool vx0 = (xi >= 0) && (xi <= 255);
        bool vx1 = (xi + 1 >= 0) && (xi + 1 <= 255);
        int y0c = min(max(yi, 0), 255),     y1c = min(max(yi + 1, 0), 255);
        int x0c = min(max(xi, 0), 255),     x1c = min(max(xi + 1, 0), 255);
        float4 w;
        w.x = (vy0 && vx0) ? wy0*wx0 : 0.f;
        w.y = (vy0 && vx1) ? wy0*fx  : 0.f;
        w.z = (vy1 && vx0) ? fy*wx0  : 0.f;
        w.w = (vy1 && vx1) ? fy*fx   : 0.f;
        *(float4*)&wPre[i*4] = w;
        aPre[i*4    ] = (y0c << 8) + x0c;
        aPre[i*4 + 1] = (y0c << 8) + x1c;
        aPre[i*4 + 2] = (y1c << 8) + x0c;
        aPre[i*4 + 3] = (y1c << 8) + x1c;
    }
    __syncthreads();
    int pix = pix0 + g;
    const float* tb = g_t + (size_t)b*NPIX*64;
    float a0 = 0.f, a1 = 0.f, a2 = 0.f, a3 = 0.f;
    for (int k = 0; k < 25; k++) {
        int base = (g*25 + k)*4;
        int4 ad = *(int4*)&aPre[base];
        float4 w = *(float4*)&wPre[base];
        float4 v00 = *(const float4*)(tb + ((size_t)ad.x << 6) + c4);
        float4 v01 = *(const float4*)(tb + ((size_t)ad.y << 6) + c4);
        float4 v10 = *(const float4*)(tb + ((size_t)ad.z << 6) + c4);
        float4 v11 = *(const float4*)(tb + ((size_t)ad.w << 6) + c4);
        float4 wv = *(float4*)&wS[k*64 + c4];
        a0 += wv.x*(w.x*v00.x + w.y*v01.x + w.z*v10.x + w.w*v11.x);
        a1 += wv.y*(w.x*v00.y + w.y*v01.y + w.z*v10.y + w.w*v11.y);
        a2 += wv.z*(w.x*v00.z + w.y*v01.z + w.z*v10.z + w.w*v11.z);
        a3 += wv.w*(w.x*v00.w + w.y*v01.w + w.z*v10.w + w.w*v11.w);
    }
    size_t o = ((size_t)b*NPIX + pix)*64 + c4;
    *(float4*)(g_a + o) = make_float4(a0, a1, a2, a3);
    __half2 h01 = __floats2half2_rn(a0, a1);
    __half2 h23 = __floats2half2_rn(a2, a3);
    *(uint2*)(g_ah + o) = make_uint2(*(uint32_t*)&h01, *(uint32_t*)&h23);
}

// ---------------- K7: deformable depthwise 7x7 dil3 (two-phase) ----------------
__global__ __launch_bounds__(256) void k_deform7(const float* __restrict__ dw)
{
    int b = blockIdx.y;
    int pix0 = blockIdx.x*16;
    int g = threadIdx.x >> 4;
    int c4 = (threadIdx.x & 15)*4;
    __shared__ float offS[16*NOFFS];
    __shared__ float wS[49*64];
    __shared__ float wPre[16*49*4];
    __shared__ int   aPre[16*49*4];
    for (int i = threadIdx.x; i < 16*NOFFS; i += 256)
        offS[i] = g_offs[((size_t)b*NPIX + pix0)*NOFFS + i];
    for (int i = threadIdx.x; i < 49*64; i += 256) {
        int k = i >> 6, c = i & 63;
        wS[i] = dw[c*49 + k];
    }
    __syncthreads();
    for (int i = threadIdx.x; i < 16*49; i += 256) {
        int gg = i/49, k = i - gg*49;
        int pix = pix0 + gg;
        int y = pix >> 8, x = pix & 255;
        int ki = k/7, kj = k%7;
        float py = (float)(y - 9 + 3*ki) + offS[gg*NOFFS + 2*k];
        float px = (float)(x - 9 + 3*kj) + offS[gg*NOFFS + 2*k + 1];
        float y0f = floorf(py), x0f = floorf(px);
        float fy = py - y0f, fx = px - x0f;
        float wy0 = 1.f - fy, wx0 = 1.f - fx;
        int yi = (int)y0f, xi = (int)x0f;
        bool vy0 = (yi >= 0) && (yi <= 255);
        bool vy1 = (yi + 1 >= 0) && (yi + 1 <= 255);
        bool vx0 = (xi >= 0) && (xi <= 255);
        bool vx1 = (xi + 1 >= 0) && (xi + 1 <= 255);
        int y0c = min(max(yi, 0), 255),     y1c = min(max(yi + 1, 0), 255);
        int x0c = min(max(xi, 0), 255),     x1c = min(max(xi + 1, 0), 255);
        float4 w;
        w.x = (vy0 && vx0) ? wy0*wx0 : 0.f;
        w.y = (vy0 && vx1) ? wy0*fx  : 0.f;
        w.z = (vy1 && vx0) ? fy*wx0  : 0.f;
        w.w = (vy1 && vx1) ? fy*fx   : 0.f;
        *(float4*)&wPre[i*4] = w;
        aPre[i*4    ] = (y0c << 8) + x0c;
        aPre[i*4 + 1] = (y0c << 8) + x1c;
        aPre[i*4 + 2] = (y1c << 8) + x0c;
        aPre[i*4 + 3] = (y1c << 8) + x1c;
    }
    __syncthreads();
    int pix = pix0 + g;
    const float* ab = g_a + (size_t)b*NPIX*64;
    float a0 = 0.f, a1 = 0.f, a2 = 0.f, a3 = 0.f;
    for (int k = 0; k < 49; k++) {
        int base = (g*49 + k)*4;
        int4 ad = *(int4*)&aPre[base];
        float4 w = *(float4*)&wPre[base];
        float4 v00 = *(const float4*)(ab + ((size_t)ad.x << 6) + c4);
        float4 v01 = *(const float4*)(ab + ((size_t)ad.y << 6) + c4);
        float4 v10 = *(const float4*)(ab + ((size_t)ad.z << 6) + c4);
        float4 v11 = *(const float4*)(ab + ((size_t)ad.w << 6) + c4);
        float4 wv = *(float4*)&wS[k*64 + c4];
        a0 += wv.x*(w.x*v00.x + w.y*v01.x + w.z*v10.x + w.w*v11.x);
        a1 += wv.y*(w.x*v00.y + w.y*v01.y + w.z*v10.y + w.w*v11.y);
        a2 += wv.z*(w.x*v00.z + w.y*v01.z + w.z*v10.z + w.w*v11.z);
        a3 += wv.w*(w.x*v00.w + w.y*v01.w + w.z*v10.w + w.w*v11.w);
    }
    *(float4*)(g_a2 + ((size_t)b*NPIX + pix)*64 + c4) = make_float4(a0, a1, a2, a3);
}

// ---------------- K8: fused g1 -> gate -> p2 -> +shortcut -> leaky -> NCHW, via mma ----------------
__global__ __launch_bounds__(256) void k_final_mma(const float* __restrict__ g1b,
                                                   const float* __restrict__ p2b,
                                                   float* __restrict__ out)
{
    extern __shared__ char sraw[];
    __half* Ah = (__half*)sraw;        // [128][72]
    __half* Al = Ah + 128*72;
    __half* Bh = Al + 128*72;          // [64][72]
    __half* Bl = Bh + 64*72;
    float* inT = (float*)sraw;         // [64][132], aliases Ah/Al
    __shared__ float mS[64], rS[64];
    const int tid = threadIdx.x;
    const int wid = tid >> 5, lane = tid & 31;
    const int grp = lane >> 2, tig = lane & 3;
    const int wm = wid & 3, wn = wid >> 2;
    const int b = blockIdx.y;
    const int pix0 = blockIdx.x*128;
    if (tid < 64) {
        mS[tid] = g_stats[(b*64 + tid)*2];
        rS[tid] = g_stats[(b*64 + tid)*2 + 1];
    }
#pragma unroll
    for (int i = 0; i < 2; i++) {
        int idx = tid + i*256;
        int n = idx >> 3, f8 = idx & 7;
        *(uint4*)(Bh + n*72 + f8*8) = *(const uint4*)(g_g1hh + n*64 + f8*8);
        *(uint4*)(Bl + n*72 + f8*8) = *(const uint4*)(g_g1ll + n*64 + f8*8);
    }
    const float* srcA = g_a2 + ((size_t)b*NPIX + pix0)*64;
#pragma unroll
    for (int i = 0; i < 4; i++) {
        int idx = tid + i*256;
        int p = idx >> 3, f8 = idx & 7;
        const float* s = srcA + (size_t)p*64 + f8*8;
        float4 v0 = *(const float4*)s, v1 = *(const float4*)(s + 4);
        float vf[8] = {v0.x, v0.y, v0.z, v0.w, v1.x, v1.y, v1.z, v1.w};
        __half hh[8], ll[8];
#pragma unroll
        for (int e = 0; e < 8; e++) {
            hh[e] = __float2half_rn(vf[e]);
            ll[e] = __float2half_rn(vf[e] - __half2float(hh[e]));
        }
        *(uint4*)(Ah + p*72 + f8*8) = *(uint4*)hh;
        *(uint4*)(Al + p*72 + f8*8) = *(uint4*)ll;
    }
    __syncthreads();
    float c[2][4][4];
#pragma unroll
    for (int mi = 0; mi < 2; mi++)
#pragma unroll
        for (int ni = 0; ni < 4; ni++)
#pragma unroll
            for (int j = 0; j < 4; j++) c[mi][ni][j] = 0.f;
    {
        const uint32_t* AuH = (const uint32_t*)Ah;
        const uint32_t* AuL = (const uint32_t*)Al;
        const uint32_t* BuH = (const uint32_t*)Bh;
        const uint32_t* BuL = (const uint32_t*)Bl;
#pragma unroll
        for (int kc = 0; kc < 4; kc++) {
            int k0 = kc*8;
            uint32_t aH[2][4], aL[2][4];
#pragma unroll
            for (int mi = 0; mi < 2; mi++) {
                int r = wm*32 + mi*16;
                aH[mi][0] = AuH[(r + grp    )*36 + k0 + tig];
                aH[mi][1] = AuH[(r + grp + 8)*36 + k0 + tig];
                aH[mi][2] = AuH[(r + grp    )*36 + k0 + tig + 4];
                aH[mi][3] = AuH[(r + grp + 8)*36 + k0 + tig + 4];
                aL[mi][0] = AuL[(r + grp    )*36 + k0 + tig];
                aL[mi][1] = AuL[(r + grp + 8)*36 + k0 + tig];
                aL[mi][2] = AuL[(r + grp    )*36 + k0 + tig + 4];
                aL[mi][3] = AuL[(r + grp + 8)*36 + k0 + tig + 4];
            }
#pragma unroll
            for (int ni = 0; ni < 4; ni++) {
                int cn = wn*32 + ni*8;
                uint32_t bh0 = BuH[(cn + grp)*36 + k0 + tig];
                uint32_t bh1 = BuH[(cn + grp)*36 + k0 + tig + 4];
                uint32_t bl0 = BuL[(cn + grp)*36 + k0 + tig];
                uint32_t bl1 = BuL[(cn + grp)*36 + k0 + tig + 4];
                mma_f16(c[0][ni], aH[0], bh0, bh1);
                mma_f16(c[1][ni], aH[1], bh0, bh1);
                mma_f16(c[0][ni], aL[0], bh0, bh1);
                mma_f16(c[1][ni], aL[1], bh0, bh1);
                mma_f16(c[0][ni], aH[0], bl0, bl1);
                mma_f16(c[1][ni], aH[1], bl0, bl1);
            }
        }
    }
    float v[2][4][4];
#pragma unroll
    for (int mi = 0; mi < 2; mi++) {
        int p0 = wm*32 + mi*16 + grp;
        size_t base0 = ((size_t)b*NPIX + pix0 + p0)*64;
        size_t base1 = ((size_t)b*NPIX + pix0 + p0 + 8)*64;
#pragma unroll
        for (int ni = 0; ni < 4; ni++) {
            int cn = wn*32 + ni*8 + 2*tig;
            float b0 = __ldg(g1b + cn), b1 = __ldg(g1b + cn + 1);
            float2 t0 = *(const float2*)(g_t + base0 + cn);
            float2 t1 = *(const float2*)(g_t + base1 + cn);
            v[mi][ni][0] = (c[mi][ni][0] + b0)*t0.x;
            v[mi][ni][1] = (c[mi][ni][1] + b1)*t0.y;
            v[mi][ni][2] = (c[mi][ni][2] + b0)*t1.x;
            v[mi][ni][3] = (c[mi][ni][3] + b1)*t1.y;
        }
    }
    __syncthreads();
#pragma unroll
    for (int mi = 0; mi < 2; mi++) {
        int p0 = wm*32 + mi*16 + grp;
#pragma unroll
        for (int ni = 0; ni < 4; ni++) {
            int cn = wn*32 + ni*8 + 2*tig;
            __half h0 = __float2half_rn(v[mi][ni][0]);
            __half h1 = __float2half_rn(v[mi][ni][1]);
            __half h2 = __float2half_rn(v[mi][ni][2]);
            __half h3 = __float2half_rn(v[mi][ni][3]);
            *(__half2*)(Ah + p0*72 + cn)       = __halves2half2(h0, h1);
            *(__half2*)(Ah + (p0+8)*72 + cn)   = __halves2half2(h2, h3);
            *(__half2*)(Al + p0*72 + cn)       = __halves2half2(
                __float2half_rn(v[mi][ni][0] - __half2float(h0)),
                __float2half_rn(v[mi][ni][1] - __half2float(h1)));
            *(__half2*)(Al + (p0+8)*72 + cn)   = __halves2half2(
                __float2half_rn(v[mi][ni][2] - __half2float(h2)),
                __float2half_rn(v[mi][ni][3] - __half2float(h3)));
        }
    }
#pragma unroll
    for (int i = 0; i < 2; i++) {
        int idx = tid + i*256;
        int n = idx >> 3, f8 = idx & 7;
        *(uint4*)(Bh + n*72 + f8*8) = *(const uint4*)(g_p2hh + n*64 + f8*8);
        *(uint4*)(Bl + n*72 + f8*8) = *(const uint4*)(g_p2ll + n*64 + f8*8);
    }
    __syncthreads();
#pragma unroll
    for (int mi = 0; mi < 2; mi++)
#pragma unroll
        for (int ni = 0; ni < 4; ni++)
#pragma unroll
            for (int j = 0; j < 4; j++) c[mi][ni][j] = 0.f;
    {
        const uint32_t* AuH = (const uint32_t*)Ah;
        const uint32_t* AuL = (const uint32_t*)Al;
        const uint32_t* BuH = (const uint32_t*)Bh;
        const uint32_t* BuL = (const uint32_t*)Bl;
#pragma unroll
        for (int kc = 0; kc < 4; kc++) {
            int k0 = kc*8;
            uint32_t aH[2][4], aL[2][4];
#pragma unroll
            for (int mi = 0; mi < 2; mi++) {
                int r = wm*32 + mi*16;
                aH[mi][0] = AuH[(r + grp    )*36 + k0 + tig];
                aH[mi][1] = AuH[(r + grp + 8)*36 + k0 + tig];
                aH[mi][2] = AuH[(r + grp    )*36 + k0 + tig + 4];
                aH[mi][3] = AuH[(r + grp + 8)*36 + k0 + tig + 4];
                aL[mi][0] = AuL[(r + grp    )*36 + k0 + tig];
                aL[mi][1] = AuL[(r + grp + 8)*36 + k0 + tig];
                aL[mi][2] = AuL[(r + grp    )*36 + k0 + tig + 4];
                aL[mi][3] = AuL[(r + grp + 8)*36 + k0 + tig + 4];
            }
#pragma unroll
            for (int ni = 0; ni < 4; ni++) {
                int cn = wn*32 + ni*8;
                uint32_t bh0 = BuH[(cn + grp)*36 + k0 + tig];
                uint32_t bh1 = BuH[(cn + grp)*36 + k0 + tig + 4];
                uint32_t bl0 = BuL[(cn + grp)*36 + k0 + tig];
                uint32_t bl1 = BuL[(cn + grp)*36 + k0 + tig + 4];
                mma_f16(c[0][ni], aH[0], bh0, bh1);
                mma_f16(c[1][ni], aH[1], bh0, bh1);
                mma_f16(c[0][ni], aL[0], bh0, bh1);
                mma_f16(c[1][ni], aL[1], bh0, bh1);
                mma_f16(c[0][ni], aH[0], bl0, bl1);
                mma_f16(c[1][ni], aH[1], bl0, bl1);
            }
        }
    }
    __syncthreads();
#pragma unroll
    for (int mi = 0; mi < 2; mi++) {
        int p0 = wm*32 + mi*16 + grp;
        size_t base0 = ((size_t)b*NPIX + pix0 + p0)*64;
        size_t base1 = ((size_t)b*NPIX + pix0 + p0 + 8)*64;
#pragma unroll
        for (int ni = 0; ni < 4; ni++) {
            int cn = wn*32 + ni*8 + 2*tig;
            float b0 = __ldg(p2b + cn), b1 = __ldg(p2b + cn + 1);
            float2 h0 = *(const float2*)(g_hraw + base0 + cn);
            float2 h1 = *(const float2*)(g_hraw + base1 + cn);
            float m0 = mS[cn], m1 = mS[cn+1], r0s = rS[cn], r1s = rS[cn+1];
            float r0 = c[mi][ni][0] + b0 + (h0.x - m0)*r0s;
            float r1 = c[mi][ni][1] + b1 + (h0.y - m1)*r1s;
            float r2 = c[mi][ni][2] + b0 + (h1.x - m0)*r0s;
            float r3 = c[mi][ni][3] + b1 + (h1.y - m1)*r1s;
            r0 = (r0 >= 0.f) ? r0 : 0.2f*r0;
            r1 = (r1 >= 0.f) ? r1 : 0.2f*r1;
            r2 = (r2 >= 0.f) ? r2 : 0.2f*r2;
            r3 = (r3 >= 0.f) ? r3 : 0.2f*r3;
            inT[cn*132 + p0]         = r0;
            inT[(cn+1)*132 + p0]     = r1;
            inT[cn*132 + p0 + 8]     = r2;
            inT[(cn+1)*132 + p0 + 8] = r3;
        }
    }
    __syncthreads();
#pragma unroll
    for (int i = 0; i < 32; i++) {
        int idx = tid + i*256;
        int o = idx >> 7, px = idx & 127;
        out[((size_t)(b*64 + o) << 16) + pix0 + px] = inT[o*132 + px];
    }
}

// ---------------- launch ----------------
extern "C" void kernel_launch(void* const* d_in, const int* in_sizes, int n_in,
                              void* d_out, int out_size)
{
    const float* x      = (const float*)d_in[0];
    const float* conv_w = (const float*)d_in[1];
    const float* p1_w   = (const float*)d_in[2];
    const float* p1_b   = (const float*)d_in[3];
    const float* off0_w = (const float*)d_in[4];
    const float* off0_b = (const float*)d_in[5];
    const float* dw0_w  = (const float*)d_in[6];
    const float* offs_w = (const float*)d_in[7];
    const float* offs_b = (const float*)d_in[8];
    const float* dws_w  = (const float*)d_in[9];
    const float* g1_w   = (const float*)d_in[10];
    const float* g1_b   = (const float*)d_in[11];
    const float* p2_w   = (const float*)d_in[12];
    const float* p2_b   = (const float*)d_in[13];
    float* out = (float*)d_out;

    void *p_th = 0, *p_ah = 0, *p_wTh = 0, *p_wT0h = 0, *p_off0 = 0, *p_offs = 0, *p_hraw = 0;
    cudaGetSymbolAddress(&p_th,   g_th);
    cudaGetSymbolAddress(&p_ah,   g_ah);
    cudaGetSymbolAddress(&p_wTh,  g_wTh);
    cudaGetSymbolAddress(&p_wT0h, g_wT0h);
    cudaGetSymbolAddress(&p_off0, g_off0);
    cudaGetSymbolAddress(&p_offs, g_offs);
    cudaGetSymbolAddress(&p_hraw, g_hraw);

    const int SMEM5h = 2*(128 + 64)*72*2;       // 55296 (double-buffered)
    const int SMEM7h = 2*(128 + 112)*72*2;      // 69120 (double-buffered)
    const int SMEM3h = (2*128*72 + 2*64*72)*2;  // 55296
    cudaFuncSetAttribute(k_conv_mma_h<50, 64, 25, 5, 1, 2>,
                         cudaFuncAttributeMaxDynamicSharedMemorySize, SMEM5h);
    cudaFuncSetAttribute(k_conv_mma_h<98, 112, 49, 7, 3, 9>,
                         cudaFuncAttributeMaxDynamicSharedMemorySize, SMEM7h);
    cudaFuncSetAttribute(k_conv3x3_mma,
                         cudaFuncAttributeMaxDynamicSharedMemorySize, SMEM3h);
    cudaFuncSetAttribute(k_p1_mma,
                         cudaFuncAttributeMaxDynamicSharedMemorySize, SMEM3h);
    cudaFuncSetAttribute(k_final_mma,
                         cudaFuncAttributeMaxDynamicSharedMemorySize, SMEM3h);

    k_repack<<<1372, 256>>>(offs_w, off0_w, conv_w, p1_w, g1_w, p2_w);
    k_nchw2nhwc<<<dim3(2048, BN), 256>>>(x);
    k_conv3x3_mma<<<dim3(16,32,BN), 256, SMEM3h>>>((float*)p_hraw);
    k_stats_final2<<<256, 64>>>();
    k_p1_mma<<<dim3(512, BN), 256, SMEM3h>>>(p1_b);
    k_conv_mma_h<50, 64, 25, 5, 1, 2><<<dim3(16,32,BN), 256, SMEM5h>>>(
        (const __half*)p_th, (const __half*)p_wT0h, off0_b, (float*)p_off0);
    k_deform5<<<dim3(4096, BN), 256>>>(dw0_w);
    k_conv_mma_h<98, 112, 49, 7, 3, 9><<<dim3(16,32,BN), 256, SMEM7h>>>(
        (const __half*)p_ah, (const __half*)p_wTh, offs_b, (float*)p_offs);
    k_deform7<<<dim3(4096, BN), 256>>>(dws_w);
    k_final_mma<<<dim3(512, BN), 256, SMEM3h>>>(g1_b, p2_b, out);
}

// round 17
// speedup vs baseline: 1.0538x; 1.0538x over previous
#include <cuda_runtime.h>
#include <cuda_fp16.h>
#include <math.h>
#include <stdint.h>

#define BN 4
#define CN 64
#define HN 256
#define WN 256
#define NPIX (HN*WN)            // 65536
#define NOFF0 50
#define NOFFS 98

// ---------------- scratch (static device globals; no allocation) ----------------
__device__ __align__(1024) float g_xt[BN*NPIX*CN];       // x transposed to NHWC
__device__ __align__(1024) float g_hraw[BN*NPIX*CN];     // conv3x3 raw output, NHWC
__device__ __align__(1024) float g_t[BN*NPIX*CN];        // gelu(p1(norm(h))), NHWC
__device__ __align__(1024) float g_a[BN*NPIX*CN];        // deform5 output fp32, NHWC
__device__ __align__(1024) float g_a2[BN*NPIX*CN];       // deform7 output, NHWC
__device__ __align__(1024) __half g_th[BN*NPIX*CN];      // g_t in fp16 (offset-conv A)
__device__ __align__(1024) __half g_ah[BN*NPIX*CN];      // g_a in fp16 (offset-conv A)
__device__ __align__(1024) float g_off0[BN*NPIX*NOFF0];  // 5x5 offsets, NHWC(50)
__device__ __align__(1024) float g_offs[BN*NPIX*NOFFS];  // 7x7 offsets, NHWC(98)
__device__ __align__(1024) __half g_wTh[49*112*64];      // 7x7 weights [t][n][k], fp16
__device__ __align__(1024) __half g_wT0h[25*64*64];      // 5x5 weights [t][n][k], fp16
__device__ __align__(1024) __half g_w3hh[9*64*64];       // 3x3 weights hi, fp16
__device__ __align__(1024) __half g_w3ll[9*64*64];       // 3x3 weights lo, fp16
__device__ __align__(1024) __half g_p1hh[64*64], g_p1ll[64*64];  // p1 weights hi/lo
__device__ __align__(1024) __half g_g1hh[64*64], g_g1ll[64*64];  // g1 weights hi/lo
__device__ __align__(1024) __half g_p2hh[64*64], g_p2ll[64*64];  // p2 weights hi/lo
__device__ float g_partial[2048*128];                    // per-CTA (sum,sumsq)/channel
__device__ float g_stats[BN*CN*2];                       // mean, rstd per (b,c)

// ---------------- helpers ----------------
__device__ __forceinline__ void mma_f16(float* c, const uint32_t* a, uint32_t b0, uint32_t b1) {
    asm volatile("mma.sync.aligned.m16n8k16.row.col.f32.f16.f16.f32 "
        "{%0,%1,%2,%3}, {%4,%5,%6,%7}, {%8,%9}, {%0,%1,%2,%3};"
        : "+f"(c[0]), "+f"(c[1]), "+f"(c[2]), "+f"(c[3])
        : "r"(a[0]), "r"(a[1]), "r"(a[2]), "r"(a[3]), "r"(b0), "r"(b1));
}
__device__ __forceinline__ float gelu_f(float v) {
    return 0.5f*v*(1.f + erff(v*0.70710678118654752f));
}
__device__ __forceinline__ uint32_t smem_u32(const void* p) {
    uint32_t a;
    asm("{ .reg .u64 t; cvta.to.shared.u64 t, %1; cvt.u32.u64 %0, t; }" : "=r"(a) : "l"(p));
    return a;
}
__device__ __forceinline__ void ldsm_x4(uint32_t& r0, uint32_t& r1, uint32_t& r2, uint32_t& r3,
                                        uint32_t addr) {
    asm volatile("ldmatrix.sync.aligned.m8n8.x4.shared.b16 {%0,%1,%2,%3}, [%4];"
        : "=r"(r0), "=r"(r1), "=r"(r2), "=r"(r3) : "r"(addr));
}
__device__ __forceinline__ void ldsm_x2(uint32_t& r0, uint32_t& r1, uint32_t addr) {
    asm volatile("ldmatrix.sync.aligned.m8n8.x2.shared.b16 {%0,%1}, [%2];"
        : "=r"(r0), "=r"(r1) : "r"(addr));
}

// ---------------- K0: repack weights ----------------
__global__ __launch_bounds__(256) void k_repack(const float* __restrict__ offs_w,
                                                const float* __restrict__ off0_w,
                                                const float* __restrict__ conv_w,
                                                const float* __restrict__ p1w,
                                                const float* __restrict__ g1w,
                                                const float* __restrict__ p2w)
{
    int i = blockIdx.x*256 + threadIdx.x;
    if (i < 49*112*64) {
        int t = i/(112*64); int rem = i%(112*64); int n = rem >> 6; int k = rem & 63;
        float v = (n < 98) ? offs_w[(n*64 + k)*49 + t] : 0.f;
        g_wTh[i] = __float2half_rn(v);
    }
    if (i < 25*64*64) {
        int t = i >> 12; int n = (i >> 6) & 63; int k = i & 63;
        float v = (n < 50) ? off0_w[(n*64 + k)*25 + t] : 0.f;
        g_wT0h[i] = __float2half_rn(v);
    }
    if (i < 9*64*64) {
        int t = i >> 12; int n = (i >> 6) & 63; int k = i & 63;
        float v = conv_w[(n*64 + k)*9 + t];
        __half h = __float2half_rn(v);
        g_w3hh[i] = h;
        g_w3ll[i] = __float2half_rn(v - __half2float(h));
    }
    if (i < 64*64) {
        float v1 = p1w[i];
        __half h1 = __float2half_rn(v1);
        g_p1hh[i] = h1; g_p1ll[i] = __float2half_rn(v1 - __half2float(h1));
        float v2 = g1w[i];
        __half h2 = __float2half_rn(v2);
        g_g1hh[i] = h2; g_g1ll[i] = __float2half_rn(v2 - __half2float(h2));
        float v3 = p2w[i];
        __half h3 = __float2half_rn(v3);
        g_p2hh[i] = h3; g_p2ll[i] = __float2half_rn(v3 - __half2float(h3));
    }
}

// ---------------- K1a: transpose x NCHW -> NHWC ----------------
__global__ __launch_bounds__(256) void k_nchw2nhwc(const float* __restrict__ x)
{
    __shared__ float sm[64*33];
    int b = blockIdx.y;
    int pix0 = blockIdx.x*32;
#pragma unroll
    for (int i = 0; i < 8; i++) {
        int idx = threadIdx.x + i*256;
        int c = idx >> 5, p = idx & 31;
        sm[c*33 + p] = x[((size_t)(b*64 + c) << 16) + pix0 + p];
    }
    __syncthreads();
#pragma unroll
    for (int i = 0; i < 8; i++) {
        int idx = threadIdx.x + i*256;
        int p = idx >> 6, c = idx & 63;
        g_xt[(((size_t)b << 16) + pix0 + p)*64 + c] = sm[c*33 + p];
    }
}

// ---------------- K1b: conv3x3 via split-fp16 mma (ldmatrix frags) + fused stats ----------------
__global__ __launch_bounds__(256) void k_conv3x3_mma(float* __restrict__ outp)
{
    extern __shared__ char sraw[];
    __half* Ah = (__half*)sraw;        // [128][72]
    __half* Al = Ah + 128*72;
    __half* Bh = Al + 128*72;          // [64][72]
    __half* Bl = Bh + 64*72;
    __shared__ float sred_s[4][64], sred_q[4][64];
    const int tid = threadIdx.x;
    const int wid = tid >> 5, lane = tid & 31;
    const int grp = lane >> 2, tig = lane & 3;
    const int jj = lane >> 3, li = lane & 7;
    const int wm = wid & 3, wn = wid >> 2;
    const int x0 = blockIdx.x*16, y0 = blockIdx.y*8, b = blockIdx.z;

    const uint32_t aHb = smem_u32(Ah) + (((wm*32 + (jj&1)*8 + li)*72 + (jj>>1)*8) << 1);
    const uint32_t aLb = smem_u32(Al) + (((wm*32 + (jj&1)*8 + li)*72 + (jj>>1)*8) << 1);
    const uint32_t bHb = smem_u32(Bh) + (((wn*32 + (jj>>1)*8 + li)*72 + (jj&1)*8) << 1);
    const uint32_t bLb = smem_u32(Bl) + (((wn*32 + (jj>>1)*8 + li)*72 + (jj&1)*8) << 1);

    float c[2][4][4];
#pragma unroll
    for (int mi = 0; mi < 2; mi++)
#pragma unroll
        for (int ni = 0; ni < 4; ni++)
#pragma unroll
            for (int j = 0; j < 4; j++) c[mi][ni][j] = 0.f;

    for (int t = 0; t < 9; t++) {
        int dy = t/3 - 1, dx = t%3 - 1;
#pragma unroll
        for (int i = 0; i < 4; i++) {
            int idx = tid + i*256;
            int p = idx >> 3, f8 = idx & 7;
            int gy = y0 + (p >> 4) + dy, gx = x0 + (p & 15) + dx;
            float4 v0 = make_float4(0.f,0.f,0.f,0.f), v1 = v0;
            if ((unsigned)gy < 256u && (unsigned)gx < 256u) {
                const float* s = g_xt + ((((size_t)b << 16) + (gy << 8) + gx) << 6) + f8*8;
                v0 = *(const float4*)s;
                v1 = *(const float4*)(s + 4);
            }
            float vf[8] = {v0.x, v0.y, v0.z, v0.w, v1.x, v1.y, v1.z, v1.w};
            __half hh[8], ll[8];
#pragma unroll
            for (int e = 0; e < 8; e++) {
                hh[e] = __float2half_rn(vf[e]);
                ll[e] = __float2half_rn(vf[e] - __half2float(hh[e]));
            }
            *(uint4*)(Ah + p*72 + f8*8) = *(uint4*)hh;
            *(uint4*)(Al + p*72 + f8*8) = *(uint4*)ll;
        }
#pragma unroll
        for (int i = 0; i < 2; i++) {
            int idx = tid + i*256;
            int n = idx >> 3, f8 = idx & 7;
            *(uint4*)(Bh + n*72 + f8*8) = *(const uint4*)(g_w3hh + ((size_t)t*64 + n)*64 + f8*8);
            *(uint4*)(Bl + n*72 + f8*8) = *(const uint4*)(g_w3ll + ((size_t)t*64 + n)*64 + f8*8);
        }
        __syncthreads();
#pragma unroll
        for (int kc = 0; kc < 4; kc++) {
            uint32_t aH[2][4], aL[2][4], bH[4][2], bL[4][2];
            ldsm_x4(aH[0][0], aH[0][1], aH[0][2], aH[0][3], aHb + kc*32);
            ldsm_x4(aH[1][0], aH[1][1], aH[1][2], aH[1][3], aHb + 2304 + kc*32);
            ldsm_x4(aL[0][0], aL[0][1], aL[0][2], aL[0][3], aLb + kc*32);
            ldsm_x4(aL[1][0], aL[1][1], aL[1][2], aL[1][3], aLb + 2304 + kc*32);
            ldsm_x4(bH[0][0], bH[0][1], bH[1][0], bH[1][1], bHb + kc*32);
            ldsm_x4(bH[2][0], bH[2][1], bH[3][0], bH[3][1], bHb + 2304 + kc*32);
            ldsm_x4(bL[0][0], bL[0][1], bL[1][0], bL[1][1], bLb + kc*32);
            ldsm_x4(bL[2][0], bL[2][1], bL[3][0], bL[3][1], bLb + 2304 + kc*32);
#pragma unroll
            for (int ni = 0; ni < 4; ni++) {
                mma_f16(c[0][ni], aH[0], bH[ni][0], bH[ni][1]);
                mma_f16(c[1][ni], aH[1], bH[ni][0], bH[ni][1]);
                mma_f16(c[0][ni], aL[0], bH[ni][0], bH[ni][1]);
                mma_f16(c[1][ni], aL[1], bH[ni][0], bH[ni][1]);
                mma_f16(c[0][ni], aH[0], bL[ni][0], bL[ni][1]);
                mma_f16(c[1][ni], aH[1], bL[ni][0], bL[ni][1]);
            }
        }
        __syncthreads();
    }
#pragma unroll
    for (int mi = 0; mi < 2; mi++) {
        int p0 = wm*32 + mi*16 + grp;
        int yA = y0 + (p0 >> 4),        xA = x0 + (p0 & 15);
        int yB = y0 + ((p0 + 8) >> 4),  xB = x0 + ((p0 + 8) & 15);
        float* ptr0 = outp + ((((size_t)b << 16) + (yA << 8) + xA) << 6);
        float* ptr1 = outp + ((((size_t)b << 16) + (yB << 8) + xB) << 6);
#pragma unroll
        for (int ni = 0; ni < 4; ni++) {
            int cn = wn*32 + ni*8 + 2*tig;
            *(float2*)(ptr0 + cn) = make_float2(c[mi][ni][0], c[mi][ni][1]);
            *(float2*)(ptr1 + cn) = make_float2(c[mi][ni][2], c[mi][ni][3]);
        }
    }
    // fused instance-norm partials
#pragma unroll
    for (int ni = 0; ni < 4; ni++) {
        float s0 = c[0][ni][0] + c[1][ni][0] + c[0][ni][2] + c[1][ni][2];
        float q0 = c[0][ni][0]*c[0][ni][0] + c[1][ni][0]*c[1][ni][0]
                 + c[0][ni][2]*c[0][ni][2] + c[1][ni][2]*c[1][ni][2];
        float s1 = c[0][ni][1] + c[1][ni][1] + c[0][ni][3] + c[1][ni][3];
        float q1 = c[0][ni][1]*c[0][ni][1] + c[1][ni][1]*c[1][ni][1]
                 + c[0][ni][3]*c[0][ni][3] + c[1][ni][3]*c[1][ni][3];
#pragma unroll
        for (int d = 16; d >= 4; d >>= 1) {
            s0 += __shfl_down_sync(0xffffffffu, s0, d);
            q0 += __shfl_down_sync(0xffffffffu, q0, d);
            s1 += __shfl_down_sync(0xffffffffu, s1, d);
            q1 += __shfl_down_sync(0xffffffffu, q1, d);
        }
        if (grp == 0) {
            int cn = wn*32 + ni*8 + 2*tig;
            sred_s[wm][cn] = s0; sred_q[wm][cn] = q0;
            sred_s[wm][cn+1] = s1; sred_q[wm][cn+1] = q1;
        }
    }
    __syncthreads();
    if (tid < 64) {
        float S = sred_s[0][tid] + sred_s[1][tid] + sred_s[2][tid] + sred_s[3][tid];
        float Q = sred_q[0][tid] + sred_q[1][tid] + sred_q[2][tid] + sred_q[3][tid];
        int blk = b*512 + blockIdx.y*16 + blockIdx.x;
        g_partial[blk*128 + tid*2    ] = S;
        g_partial[blk*128 + tid*2 + 1] = Q;
    }
}

// ---------------- K2: stats final ----------------
__global__ __launch_bounds__(64) void k_stats_final2()
{
    int bc = blockIdx.x;
    int b = bc >> 6, c = bc & 63;
    int tid = threadIdx.x;
    float s = 0.f, q = 0.f;
    for (int i = tid; i < 512; i += 64) {
        s += g_partial[(b*512 + i)*128 + c*2];
        q += g_partial[(b*512 + i)*128 + c*2 + 1];
    }
    __shared__ float sh[4];
#pragma unroll
    for (int d = 16; d; d >>= 1) {
        s += __shfl_down_sync(0xffffffffu, s, d);
        q += __shfl_down_sync(0xffffffffu, q, d);
    }
    if ((tid & 31) == 0) { sh[(tid>>5)*2] = s; sh[(tid>>5)*2 + 1] = q; }
    __syncthreads();
    if (tid == 0) {
        float S = sh[0] + sh[2], Q = sh[1] + sh[3];
        float m = S * (1.f/65536.f);
        float var = Q * (1.f/65536.f) - m*m;
        g_stats[bc*2    ] = m;
        g_stats[bc*2 + 1] = rsqrtf(var + 1e-5f);
    }
}

// ---------------- K3: t = gelu(p1 @ norm(h) + b) via split-fp16 mma + ldmatrix ----------------
__global__ __launch_bounds__(256) void k_p1_mma(const float* __restrict__ p1b)
{
    extern __shared__ char sraw[];
    __half* Ah = (__half*)sraw;        // [128][72]
    __half* Al = Ah + 128*72;
    __half* Bh = Al + 128*72;          // [64][72]
    __half* Bl = Bh + 64*72;
    __shared__ float mS[64], rS[64];
    const int tid = threadIdx.x;
    const int wid = tid >> 5, lane = tid & 31;
    const int grp = lane >> 2, tig = lane & 3;
    const int jj = lane >> 3, li = lane & 7;
    const int wm = wid & 3, wn = wid >> 2;
    const int b = blockIdx.y;
    const int pix0 = blockIdx.x*128;
    const uint32_t aHb = smem_u32(Ah) + (((wm*32 + (jj&1)*8 + li)*72 + (jj>>1)*8) << 1);
    const uint32_t aLb = smem_u32(Al) + (((wm*32 + (jj&1)*8 + li)*72 + (jj>>1)*8) << 1);
    const uint32_t bHb = smem_u32(Bh) + (((wn*32 + (jj>>1)*8 + li)*72 + (jj&1)*8) << 1);
    const uint32_t bLb = smem_u32(Bl) + (((wn*32 + (jj>>1)*8 + li)*72 + (jj&1)*8) << 1);
    if (tid < 64) {
        mS[tid] = g_stats[(b*64 + tid)*2];
        rS[tid] = g_stats[(b*64 + tid)*2 + 1];
    }
    __syncthreads();
#pragma unroll
    for (int i = 0; i < 2; i++) {
        int idx = tid + i*256;
        int n = idx >> 3, f8 = idx & 7;
        *(uint4*)(Bh + n*72 + f8*8) = *(const uint4*)(g_p1hh + n*64 + f8*8);
        *(uint4*)(Bl + n*72 + f8*8) = *(const uint4*)(g_p1ll + n*64 + f8*8);
    }
    const float* src = g_hraw + ((size_t)b*NPIX + pix0)*64;
#pragma unroll
    for (int i = 0; i < 4; i++) {
        int idx = tid + i*256;
        int p = idx >> 3, f8 = idx & 7;
        const float* s = src + (size_t)p*64 + f8*8;
        float4 v0 = *(const float4*)s, v1 = *(const float4*)(s + 4);
        float vf[8] = {v0.x, v0.y, v0.z, v0.w, v1.x, v1.y, v1.z, v1.w};
        __half hh[8], ll[8];
        int c0 = f8*8;
#pragma unroll
        for (int e = 0; e < 8; e++) {
            float nv = (vf[e] - mS[c0 + e])*rS[c0 + e];
            hh[e] = __float2half_rn(nv);
            ll[e] = __float2half_rn(nv - __half2float(hh[e]));
        }
        *(uint4*)(Ah + p*72 + f8*8) = *(uint4*)hh;
        *(uint4*)(Al + p*72 + f8*8) = *(uint4*)ll;
    }
    __syncthreads();
    float c[2][4][4];
#pragma unroll
    for (int mi = 0; mi < 2; mi++)
#pragma unroll
        for (int ni = 0; ni < 4; ni++)
#pragma unroll
            for (int j = 0; j < 4; j++) c[mi][ni][j] = 0.f;
#pragma unroll
    for (int kc = 0; kc < 4; kc++) {
        uint32_t aH[2][4], aL[2][4], bH[4][2], bL[4][2];
        ldsm_x4(aH[0][0], aH[0][1], aH[0][2], aH[0][3], aHb + kc*32);
        ldsm_x4(aH[1][0], aH[1][1], aH[1][2], aH[1][3], aHb + 2304 + kc*32);
        ldsm_x4(aL[0][0], aL[0][1], aL[0][2], aL[0][3], aLb + kc*32);
        ldsm_x4(aL[1][0], aL[1][1], aL[1][2], aL[1][3], aLb + 2304 + kc*32);
        ldsm_x4(bH[0][0], bH[0][1], bH[1][0], bH[1][1], bHb + kc*32);
        ldsm_x4(bH[2][0], bH[2][1], bH[3][0], bH[3][1], bHb + 2304 + kc*32);
        ldsm_x4(bL[0][0], bL[0][1], bL[1][0], bL[1][1], bLb + kc*32);
        ldsm_x4(bL[2][0], bL[2][1], bL[3][0], bL[3][1], bLb + 2304 + kc*32);
#pragma unroll
        for (int ni = 0; ni < 4; ni++) {
            mma_f16(c[0][ni], aH[0], bH[ni][0], bH[ni][1]);
            mma_f16(c[1][ni], aH[1], bH[ni][0], bH[ni][1]);
            mma_f16(c[0][ni], aL[0], bH[ni][0], bH[ni][1]);
            mma_f16(c[1][ni], aL[1], bH[ni][0], bH[ni][1]);
            mma_f16(c[0][ni], aH[0], bL[ni][0], bL[ni][1]);
            mma_f16(c[1][ni], aH[1], bL[ni][0], bL[ni][1]);
        }
    }
#pragma unroll
    for (int mi = 0; mi < 2; mi++) {
        int p0 = wm*32 + mi*16 + grp;
        size_t base0 = ((size_t)b*NPIX + pix0 + p0)*64;
        size_t base1 = ((size_t)b*NPIX + pix0 + p0 + 8)*64;
#pragma unroll
        for (int ni = 0; ni < 4; ni++) {
            int cn = wn*32 + ni*8 + 2*tig;
            float b0 = __ldg(p1b + cn), b1 = __ldg(p1b + cn + 1);
            float r0 = gelu_f(c[mi][ni][0] + b0);
            float r1 = gelu_f(c[mi][ni][1] + b1);
            float r2 = gelu_f(c[mi][ni][2] + b0);
            float r3 = gelu_f(c[mi][ni][3] + b1);
            *(float2*)(g_t + base0 + cn) = make_float2(r0, r1);
            *(float2*)(g_t + base1 + cn) = make_float2(r2, r3);
            __half2 h01 = __floats2half2_rn(r0, r1);
            __half2 h23 = __floats2half2_rn(r2, r3);
            *(uint32_t*)(g_th + base0 + cn) = *(uint32_t*)&h01;
            *(uint32_t*)(g_th + base1 + cn) = *(uint32_t*)&h23;
        }
    }
}

// ---------------- implicit-GEMM offset conv: fp16 mma + ldmatrix (R15 single-buffer) ----------------
template<int COUT, int NPAD, int NT, int KW, int DIL, int PAD>
__global__ __launch_bounds__(256) void k_conv_mma_h(const __half* __restrict__ src,
                                                    const __half* __restrict__ wT,
                                                    const float* __restrict__ bias,
                                                    float* __restrict__ outp)
{
    constexpr int NWN = NPAD/2;
    constexpr int NTILE = NWN/8;
    constexpr int BCH = NPAD*8;
    extern __shared__ char sraw[];
    __half* As = (__half*)sraw;       // [128][72]
    __half* Bs = As + 128*72;         // [NPAD][72]
    const int tid = threadIdx.x;
    const int wid = tid >> 5, lane = tid & 31;
    const int grp = lane >> 2, tig = lane & 3;
    const int jj = lane >> 3, li = lane & 7;
    const int wm = wid & 3, wn = wid >> 2;
    const int x0 = blockIdx.x*16, y0 = blockIdx.y*8, b = blockIdx.z;

    const uint32_t aB = smem_u32(As) + (((wm*32 + (jj&1)*8 + li)*72 + (jj>>1)*8) << 1);
    const uint32_t bB = smem_u32(Bs) + (((wn*NWN + (jj>>1)*8 + li)*72 + (jj&1)*8) << 1);
    const uint32_t bB2 = smem_u32(Bs) + (((wn*NWN + (NTILE-1)*8 + li)*72 + ((lane>>3)&1)*8) << 1);

    float c[2][NTILE][4];
#pragma unroll
    for (int mi = 0; mi < 2; mi++)
#pragma unroll
        for (int ni = 0; ni < NTILE; ni++)
#pragma unroll
            for (int j = 0; j < 4; j++) c[mi][ni][j] = 0.f;

    for (int t = 0; t < NT; t++) {
        int dy = DIL*(t/KW) - PAD, dx = DIL*(t%KW) - PAD;
#pragma unroll
        for (int i = 0; i < 4; i++) {
            int idx = tid + i*256;
            int p = idx >> 3, f8 = idx & 7;
            int gy = y0 + (p >> 4) + dy, gx = x0 + (p & 15) + dx;
            uint4 v = make_uint4(0u, 0u, 0u, 0u);
            if ((unsigned)gy < 256u && (unsigned)gx < 256u)
                v = *(const uint4*)(src + ((((size_t)b << 16) + (gy << 8) + gx) << 6) + f8*8);
            *(uint4*)(As + p*72 + f8*8) = v;
        }
#pragma unroll
        for (int i = 0; i < (BCH + 255)/256; i++) {
            int idx = tid + i*256;
            if (idx < BCH) {
                int n = idx >> 3, f8 = idx & 7;
                *(uint4*)(Bs + n*72 + f8*8) =
                    *(const uint4*)(wT + ((size_t)t*NPAD + n)*64 + f8*8);
            }
        }
        __syncthreads();
#pragma unroll
        for (int kc = 0; kc < 4; kc++) {
            uint32_t a[2][4], bf[NTILE][2];
            ldsm_x4(a[0][0], a[0][1], a[0][2], a[0][3], aB + kc*32);
            ldsm_x4(a[1][0], a[1][1], a[1][2], a[1][3], aB + 2304 + kc*32);
#pragma unroll
            for (int np = 0; np < NTILE/2; np++)
                ldsm_x4(bf[2*np][0], bf[2*np][1], bf[2*np+1][0], bf[2*np+1][1],
                        bB + np*2304 + kc*32);
            if constexpr (NTILE & 1)
                ldsm_x2(bf[NTILE-1][0], bf[NTILE-1][1], bB2 + kc*32);
#pragma unroll
            for (int ni = 0; ni < NTILE; ni++) {
                mma_f16(c[0][ni], a[0], bf[ni][0], bf[ni][1]);
                mma_f16(c[1][ni], a[1], bf[ni][0], bf[ni][1]);
            }
        }
        __syncthreads();
    }
#pragma unroll
    for (int mi = 0; mi < 2; mi++) {
        int p0 = wm*32 + mi*16 + grp;
        int yA = y0 + (p0 >> 4),        xA = x0 + (p0 & 15);
        int yB = y0 + ((p0 + 8) >> 4),  xB = x0 + ((p0 + 8) & 15);
        float* ptr0 = outp + (((size_t)b << 16) + (yA << 8) + xA)*COUT;
        float* ptr1 = outp + (((size_t)b << 16) + (yB << 8) + xB)*COUT;
#pragma unroll
        for (int ni = 0; ni < NTILE; ni++) {
            int cn = wn*NWN + ni*8 + 2*tig;
            if (cn < COUT) {
                float b0 = bias[cn], b1 = bias[cn+1];
                *(float2*)(ptr0 + cn) = make_float2(c[mi][ni][0] + b0, c[mi][ni][1] + b1);
                *(float2*)(ptr1 + cn) = make_float2(c[mi][ni][2] + b0, c[mi][ni][3] + b1);
            }
        }
    }
}

// ---------------- K5: deformable depthwise 5x5 (two-phase) ----------------
__global__ __launch_bounds__(256) void k_deform5(const float* __restrict__ dw)
{
    int b = blockIdx.y;
    int pix0 = blockIdx.x*16;
    int g = threadIdx.x >> 4;
    int c4 = (threadIdx.x & 15)*4;
    __shared__ float offS[16*NOFF0];
    __shared__ float wS[25*64];
    __shared__ float wPre[16*25*4];
    __shared__ int   aPre[16*25*4];
    for (int i = threadIdx.x; i < 16*NOFF0; i += 256)
        offS[i] = g_off0[((size_t)b*NPIX + pix0)*NOFF0 + i];
    for (int i = threadIdx.x; i < 25*64; i += 256) {
        int k = i >> 6, c = i & 63;
        wS[i] = dw[c*25 + k];
    }
    __syncthreads();
    for (int i = threadIdx.x; i < 16*25; i += 256) {
        int gg = i/25, k = i - gg*25;
        int pix = pix0 + gg;
        int y = pix >> 8, x = pix & 255;
        int ki = k/5, kj = k%5;
        float py = (float)(y - 2 + ki) + offS[gg*NOFF0 + 2*k];
        float px = (float)(x - 2 + kj) + offS[gg*NOFF0 + 2*k + 1];
        float y0f = floorf(py), x0f = floorf(px);
        float fy = py - y0f, fx = px - x0f;
        float wy0 = 1.f - fy, wx0 = 1.f - fx;
        int yi = (int)y0f, xi = (int)x0f;
        bool vy0 = (yi >= 0) && (yi <= 255);
        bool vy1 = (yi + 1 >= 0) && (yi + 1 <= 255);
        bool vx0 = (xi >= 0) && (xi <= 255);
        bool vx1 = (xi + 1 >= 0) && (xi + 1 <= 255);
        int y0c = min(max(yi, 0), 255),     y1c = min(max(yi + 1, 0), 255);
        int x0c = min(max(xi, 0), 255),     x1c = min(max(xi + 1, 0), 255);
        float4 w;
        w.x = (vy0 && vx0) ? wy0*wx0 : 0.f;
        w.y = (vy0 && vx1) ? wy0*fx  : 0.f;
        w.z = (vy1 && vx0) ? fy*wx0  : 0.f;
        w.w = (vy1 && vx1) ? fy*fx   : 0.f;
        *(float4*)&wPre[i*4] = w;
        aPre[i*4    ] = (y0c << 8) + x0c;
        aPre[i*4 + 1] = (y0c << 8) + x1c;
        aPre[i*4 + 2] = (y1c << 8) + x0c;
        aPre[i*4 + 3] = (y1c << 8) + x1c;
    }
    __syncthreads();
    int pix = pix0 + g;
    const float* tb = g_t + (size_t)b*NPIX*64;
    float a0 = 0.f, a1 = 0.f, a2 = 0.f, a3 = 0.f;
    for (int k = 0; k < 25; k++) {
        int base = (g*25 + k)*4;
        int4 ad = *(int4*)&aPre[base];
        float4 w = *(float4*)&wPre[base];
        float4 v00 = *(const float4*)(tb + ((size_t)ad.x << 6) + c4);
        float4 v01 = *(const float4*)(tb + ((size_t)ad.y << 6) + c4);
        float4 v10 = *(const float4*)(tb + ((size_t)ad.z << 6) + c4);
        float4 v11 = *(const float4*)(tb + ((size_t)ad.w << 6) + c4);
        float4 wv = *(float4*)&wS[k*64 + c4];
        a0 += wv.x*(w.x*v00.x + w.y*v01.x + w.z*v10.x + w.w*v11.x);
        a1 += wv.y*(w.x*v00.y + w.y*v01.y + w.z*v10.y + w.w*v11.y);
        a2 += wv.z*(w.x*v00.z + w.y*v01.z + w.z*v10.z + w.w*v11.z);
        a3 += wv.w*(w.x*v00.w + w.y*v01.w + w.z*v10.w + w.w*v11.w);
    }
    size_t o = ((size_t)b*NPIX + pix)*64 + c4;
    *(float4*)(g_a + o) = make_float4(a0, a1, a2, a3);
    __half2 h01 = __floats2half2_rn(a0, a1);
    __half2 h23 = __floats2half2_rn(a2, a3);
    *(uint2*)(g_ah + o) = make_uint2(*(uint32_t*)&h01, *(uint32_t*)&h23);
}

// ---------------- K7: deformable depthwise 7x7 dil3 (two-phase) ----------------
__global__ __launch_bounds__(256) void k_deform7(const float* __restrict__ dw)
{
    int b = blockIdx.y;
    int pix0 = blockIdx.x*16;
    int g = threadIdx.x >> 4;
    int c4 = (threadIdx.x & 15)*4;
    __shared__ float offS[16*NOFFS];
    __shared__ float wS[49*64];
    __shared__ float wPre[16*49*4];
    __shared__ int   aPre[16*49*4];
    for (int i = threadIdx.x; i < 16*NOFFS; i += 256)
        offS[i] = g_offs[((size_t)b*NPIX + pix0)*NOFFS + i];
    for (int i = threadIdx.x; i < 49*64; i += 256) {
        int k = i >> 6, c = i & 63;
        wS[i] = dw[c*49 + k];
    }
    __syncthreads();
    for (int i = threadIdx.x; i < 16*49; i += 256) {
        int gg = i/49, k = i - gg*49;
        int pix = pix0 + gg;
        int y = pix >> 8, x = pix & 255;
        int ki = k/7, kj = k%7;
        float py = (float)(y - 9 + 3*ki) + offS[gg*NOFFS + 2*k];
        float px = (float)(x - 9 + 3*kj) + offS[gg*NOFFS + 2*k + 1];
        float y0f = floorf(py), x0f = floorf(px);
        float fy = py - y0f, fx = px - x0f;
        float wy0 = 1.f - fy, wx0 = 1.f - fx;
        int yi = (int)y0f, xi = (int)x0f;
        bool vy0 = (yi >= 0) && (yi <= 255);
        bool vy1 = (yi + 1 >= 0) && (yi + 1 <= 255);
        bool vx0 = (xi >= 0) && (xi <= 255);
        bool vx1 = (xi + 1 >= 0) && (xi + 1 <= 255);
        int y0c = min(max(yi, 0), 255),     y1c = min(max(yi + 1, 0), 255);
        int x0c = min(max(xi, 0), 255),     x1c = min(max(xi + 1, 0), 255);
        float4 w;
        w.x = (vy0 && vx0) ? wy0*wx0 : 0.f;
        w.y = (vy0 && vx1) ? wy0*fx  : 0.f;
        w.z = (vy1 && vx0) ? fy*wx0  : 0.f;
        w.w = (vy1 && vx1) ? fy*fx   : 0.f;
        *(float4*)&wPre[i*4] = w;
        aPre[i*4    ] = (y0c << 8) + x0c;
        aPre[i*4 + 1] = (y0c << 8) + x1c;
        aPre[i*4 + 2] = (y1c << 8) + x0c;
        aPre[i*4 + 3] = (y1c << 8) + x1c;
    }
    __syncthreads();
    int pix = pix0 + g;
    const float* ab = g_a + (size_t)b*NPIX*64;
    float a0 = 0.f, a1 = 0.f, a2 = 0.f, a3 = 0.f;
    for (int k = 0; k < 49; k++) {
        int base = (g*49 + k)*4;
        int4 ad = *(int4*)&aPre[base];
        float4 w = *(float4*)&wPre[base];
        float4 v00 = *(const float4*)(ab + ((size_t)ad.x << 6) + c4);
        float4 v01 = *(const float4*)(ab + ((size_t)ad.y << 6) + c4);
        float4 v10 = *(const float4*)(ab + ((size_t)ad.z << 6) + c4);
        float4 v11 = *(const float4*)(ab + ((size_t)ad.w << 6) + c4);
        float4 wv = *(float4*)&wS[k*64 + c4];
        a0 += wv.x*(w.x*v00.x + w.y*v01.x + w.z*v10.x + w.w*v11.x);
        a1 += wv.y*(w.x*v00.y + w.y*v01.y + w.z*v10.y + w.w*v11.y);
        a2 += wv.z*(w.x*v00.z + w.y*v01.z + w.z*v10.z + w.w*v11.z);
        a3 += wv.w*(w.x*v00.w + w.y*v01.w + w.z*v10.w + w.w*v11.w);
    }
    *(float4*)(g_a2 + ((size_t)b*NPIX + pix)*64 + c4) = make_float4(a0, a1, a2, a3);
}

// ---------------- K8: fused g1 -> gate -> p2 -> +shortcut -> leaky -> NCHW, via mma + ldmatrix ----------------
__global__ __launch_bounds__(256) void k_final_mma(const float* __restrict__ g1b,
                                                   const float* __restrict__ p2b,
                                                   float* __restrict__ out)
{
    extern __shared__ char sraw[];
    __half* Ah = (__half*)sraw;        // [128][72]
    __half* Al = Ah + 128*72;
    __half* Bh = Al + 128*72;          // [64][72]
    __half* Bl = Bh + 64*72;
    float* inT = (float*)sraw;         // [64][132], aliases Ah/Al
    __shared__ float mS[64], rS[64];
    const int tid = threadIdx.x;
    const int wid = tid >> 5, lane = tid & 31;
    const int grp = lane >> 2, tig = lane & 3;
    const int jj = lane >> 3, li = lane & 7;
    const int wm = wid & 3, wn = wid >> 2;
    const int b = blockIdx.y;
    const int pix0 = blockIdx.x*128;
    const uint32_t aHb = smem_u32(Ah) + (((wm*32 + (jj&1)*8 + li)*72 + (jj>>1)*8) << 1);
    const uint32_t aLb = smem_u32(Al) + (((wm*32 + (jj&1)*8 + li)*72 + (jj>>1)*8) << 1);
    const uint32_t bHb = smem_u32(Bh) + (((wn*32 + (jj>>1)*8 + li)*72 + (jj&1)*8) << 1);
    const uint32_t bLb = smem_u32(Bl) + (((wn*32 + (jj>>1)*8 + li)*72 + (jj&1)*8) << 1);
    if (tid < 64) {
        mS[tid] = g_stats[(b*64 + tid)*2];
        rS[tid] = g_stats[(b*64 + tid)*2 + 1];
    }
#pragma unroll
    for (int i = 0; i < 2; i++) {
        int idx = tid + i*256;
        int n = idx >> 3, f8 = idx & 7;
        *(uint4*)(Bh + n*72 + f8*8) = *(const uint4*)(g_g1hh + n*64 + f8*8);
        *(uint4*)(Bl + n*72 + f8*8) = *(const uint4*)(g_g1ll + n*64 + f8*8);
    }
    const float* srcA = g_a2 + ((size_t)b*NPIX + pix0)*64;
#pragma unroll
    for (int i = 0; i < 4; i++) {
        int idx = tid + i*256;
        int p = idx >> 3, f8 = idx & 7;
        const float* s = srcA + (size_t)p*64 + f8*8;
        float4 v0 = *(const float4*)s, v1 = *(const float4*)(s + 4);
        float vf[8] = {v0.x, v0.y, v0.z, v0.w, v1.x, v1.y, v1.z, v1.w};
        __half hh[8], ll[8];
#pragma unroll
        for (int e = 0; e < 8; e++) {
            hh[e] = __float2half_rn(vf[e]);
            ll[e] = __float2half_rn(vf[e] - __half2float(hh[e]));
        }
        *(uint4*)(Ah + p*72 + f8*8) = *(uint4*)hh;
        *(uint4*)(Al + p*72 + f8*8) = *(uint4*)ll;
    }
    __syncthreads();
    float c[2][4][4];
#pragma unroll
    for (int mi = 0; mi < 2; mi++)
#pragma unroll
        for (int ni = 0; ni < 4; ni++)
#pragma unroll
            for (int j = 0; j < 4; j++) c[mi][ni][j] = 0.f;
#pragma unroll
    for (int kc = 0; kc < 4; kc++) {
        uint32_t aH[2][4], aL[2][4], bH[4][2], bL[4][2];
        ldsm_x4(aH[0][0], aH[0][1], aH[0][2], aH[0][3], aHb + kc*32);
        ldsm_x4(aH[1][0], aH[1][1], aH[1][2], aH[1][3], aHb + 2304 + kc*32);
        ldsm_x4(aL[0][0], aL[0][1], aL[0][2], aL[0][3], aLb + kc*32);
        ldsm_x4(aL[1][0], aL[1][1], aL[1][2], aL[1][3], aLb + 2304 + kc*32);
        ldsm_x4(bH[0][0], bH[0][1], bH[1][0], bH[1][1], bHb + kc*32);
        ldsm_x4(bH[2][0], bH[2][1], bH[3][0], bH[3][1], bHb + 2304 + kc*32);
        ldsm_x4(bL[0][0], bL[0][1], bL[1][0], bL[1][1], bLb + kc*32);
        ldsm_x4(bL[2][0], bL[2][1], bL[3][0], bL[3][1], bLb + 2304 + kc*32);
#pragma unroll
        for (int ni = 0; ni < 4; ni++) {
            mma_f16(c[0][ni], aH[0], bH[ni][0], bH[ni][1]);
            mma_f16(c[1][ni], aH[1], bH[ni][0], bH[ni][1]);
            mma_f16(c[0][ni], aL[0], bH[ni][0], bH[ni][1]);
            mma_f16(c[1][ni], aL[1], bH[ni][0], bH[ni][1]);
            mma_f16(c[0][ni], aH[0], bL[ni][0], bL[ni][1]);
            mma_f16(c[1][ni], aH[1], bL[ni][0], bL[ni][1]);
        }
    }
    // gate: v = (g + g1b) * t
    float v[2][4][4];
#pragma unroll
    for (int mi = 0; mi < 2; mi++) {
        int p0 = wm*32 + mi*16 + grp;
        size_t base0 = ((size_t)b*NPIX + pix0 + p0)*64;
        size_t base1 = ((size_t)b*NPIX + pix0 + p0 + 8)*64;
#pragma unroll
        for (int ni = 0; ni < 4; ni++) {
            int cn = wn*32 + ni*8 + 2*tig;
            float b0 = __ldg(g1b + cn), b1 = __ldg(g1b + cn + 1);
            float2 t0 = *(const float2*)(g_t + base0 + cn);
            float2 t1 = *(const float2*)(g_t + base1 + cn);
            v[mi][ni][0] = (c[mi][ni][0] + b0)*t0.x;
            v[mi][ni][1] = (c[mi][ni][1] + b1)*t0.y;
            v[mi][ni][2] = (c[mi][ni][2] + b0)*t1.x;
            v[mi][ni][3] = (c[mi][ni][3] + b1)*t1.y;
        }
    }
    __syncthreads();
    // restage A = v split; B = p2 split
#pragma unroll
    for (int mi = 0; mi < 2; mi++) {
        int p0 = wm*32 + mi*16 + grp;
#pragma unroll
        for (int ni = 0; ni < 4; ni++) {
            int cn = wn*32 + ni*8 + 2*tig;
            __half h0 = __float2half_rn(v[mi][ni][0]);
            __half h1 = __float2half_rn(v[mi][ni][1]);
            __half h2 = __float2half_rn(v[mi][ni][2]);
            __half h3 = __float2half_rn(v[mi][ni][3]);
            *(__half2*)(Ah + p0*72 + cn)       = __halves2half2(h0, h1);
            *(__half2*)(Ah + (p0+8)*72 + cn)   = __halves2half2(h2, h3);
            *(__half2*)(Al + p0*72 + cn)       = __halves2half2(
                __float2half_rn(v[mi][ni][0] - __half2float(h0)),
                __float2half_rn(v[mi][ni][1] - __half2float(h1)));
            *(__half2*)(Al + (p0+8)*72 + cn)   = __halves2half2(
                __float2half_rn(v[mi][ni][2] - __half2float(h2)),
                __float2half_rn(v[mi][ni][3] - __half2float(h3)));
        }
    }
#pragma unroll
    for (int i = 0; i < 2; i++) {
        int idx = tid + i*256;
        int n = idx >> 3, f8 = idx & 7;
        *(uint4*)(Bh + n*72 + f8*8) = *(const uint4*)(g_p2hh + n*64 + f8*8);
        *(uint4*)(Bl + n*72 + f8*8) = *(const uint4*)(g_p2ll + n*64 + f8*8);
    }
    __syncthreads();
#pragma unroll
    for (int mi = 0; mi < 2; mi++)
#pragma unroll
        for (int ni = 0; ni < 4; ni++)
#pragma unroll
            for (int j = 0; j < 4; j++) c[mi][ni][j] = 0.f;
#pragma unroll
    for (int kc = 0; kc < 4; kc++) {
        uint32_t aH[2][4], aL[2][4], bH[4][2], bL[4][2];
        ldsm_x4(aH[0][0], aH[0][1], aH[0][2], aH[0][3], aHb + kc*32);
        ldsm_x4(aH[1][0], aH[1][1], aH[1][2], aH[1][3], aHb + 2304 + kc*32);
        ldsm_x4(aL[0][0], aL[0][1], aL[0][2], aL[0][3], aLb + kc*32);
        ldsm_x4(aL[1][0], aL[1][1], aL[1][2], aL[1][3], aLb + 2304 + kc*32);
        ldsm_x4(bH[0][0], bH[0][1], bH[1][0], bH[1][1], bHb + kc*32);
        ldsm_x4(bH[2][0], bH[2][1], bH[3][0], bH[3][1], bHb + 2304 + kc*32);
        ldsm_x4(bL[0][0], bL[0][1], bL[1][0], bL[1][1], bLb + kc*32);
        ldsm_x4(bL[2][0], bL[2][1], bL[3][0], bL[3][1], bLb + 2304 + kc*32);
#pragma unroll
        for (int ni = 0; ni < 4; ni++) {
            mma_f16(c[0][ni], aH[0], bH[ni][0], bH[ni][1]);
            mma_f16(c[1][ni], aH[1], bH[ni][0], bH[ni][1]);
            mma_f16(c[0][ni], aL[0], bH[ni][0], bH[ni][1]);
            mma_f16(c[1][ni], aL[1], bH[ni][0], bH[ni][1]);
            mma_f16(c[0][ni], aH[0], bL[ni][0], bL[ni][1]);
            mma_f16(c[1][ni], aH[1], bL[ni][0], bL[ni][1]);
        }
    }
    __syncthreads();
    // epilogue: +p2b + norm shortcut + leaky; transpose to inT[o][px]
#pragma unroll
    for (int mi = 0; mi < 2; mi++) {
        int p0 = wm*32 + mi*16 + grp;
        size_t base0 = ((size_t)b*NPIX + pix0 + p0)*64;
        size_t base1 = ((size_t)b*NPIX + pix0 + p0 + 8)*64;
#pragma unroll
        for (int ni = 0; ni < 4; ni++) {
            int cn = wn*32 + ni*8 + 2*tig;
            float b0 = __ldg(p2b + cn), b1 = __ldg(p2b + cn + 1);
            float2 h0 = *(const float2*)(g_hraw + base0 + cn);
            float2 h1 = *(const float2*)(g_hraw + base1 + cn);
            float m0 = mS[cn], m1 = mS[cn+1], r0s = rS[cn], r1s = rS[cn+1];
            float r0 = c[mi][ni][0] + b0 + (h0.x - m0)*r0s;
            float r1 = c[mi][ni][1] + b1 + (h0.y - m1)*r1s;
            float r2 = c[mi][ni][2] + b0 + (h1.x - m0)*r0s;
            float r3 = c[mi][ni][3] + b1 + (h1.y - m1)*r1s;
            r0 = (r0 >= 0.f) ? r0 : 0.2f*r0;
            r1 = (r1 >= 0.f) ? r1 : 0.2f*r1;
            r2 = (r2 >= 0.f) ? r2 : 0.2f*r2;
            r3 = (r3 >= 0.f) ? r3 : 0.2f*r3;
            inT[cn*132 + p0]         = r0;
            inT[(cn+1)*132 + p0]     = r1;
            inT[cn*132 + p0 + 8]     = r2;
            inT[(cn+1)*132 + p0 + 8] = r3;
        }
    }
    __syncthreads();
#pragma unroll
    for (int i = 0; i < 32; i++) {
        int idx = tid + i*256;
        int o = idx >> 7, px = idx & 127;
        out[((size_t)(b*64 + o) << 16) + pix0 + px] = inT[o*132 + px];
    }
}

// ---------------- launch ----------------
extern "C" void kernel_launch(void* const* d_in, const int* in_sizes, int n_in,
                              void* d_out, int out_size)
{
    const float* x      = (const float*)d_in[0];
    const float* conv_w = (const float*)d_in[1];
    const float* p1_w   = (const float*)d_in[2];
    const float* p1_b   = (const float*)d_in[3];
    const float* off0_w = (const float*)d_in[4];
    const float* off0_b = (const float*)d_in[5];
    const float* dw0_w  = (const float*)d_in[6];
    const float* offs_w = (const float*)d_in[7];
    const float* offs_b = (const float*)d_in[8];
    const float* dws_w  = (const float*)d_in[9];
    const float* g1_w   = (const float*)d_in[10];
    const float* g1_b   = (const float*)d_in[11];
    const float* p2_w   = (const float*)d_in[12];
    const float* p2_b   = (const float*)d_in[13];
    float* out = (float*)d_out;

    void *p_th = 0, *p_ah = 0, *p_wTh = 0, *p_wT0h = 0, *p_off0 = 0, *p_offs = 0, *p_hraw = 0;
    cudaGetSymbolAddress(&p_th,   g_th);
    cudaGetSymbolAddress(&p_ah,   g_ah);
    cudaGetSymbolAddress(&p_wTh,  g_wTh);
    cudaGetSymbolAddress(&p_wT0h, g_wT0h);
    cudaGetSymbolAddress(&p_off0, g_off0);
    cudaGetSymbolAddress(&p_offs, g_offs);
    cudaGetSymbolAddress(&p_hraw, g_hraw);

    const int SMEM5h = (128*72 + 64*72)*2;      // 27648
    const int SMEM7h = (128*72 + 112*72)*2;     // 34560
    const int SMEM3h = (2*128*72 + 2*64*72)*2;  // 55296
    cudaFuncSetAttribute(k_conv_mma_h<50, 64, 25, 5, 1, 2>,
                         cudaFuncAttributeMaxDynamicSharedMemorySize, SMEM5h);
    cudaFuncSetAttribute(k_conv_mma_h<98, 112, 49, 7, 3, 9>,
                         cudaFuncAttributeMaxDynamicSharedMemorySize, SMEM7h);
    cudaFuncSetAttribute(k_conv3x3_mma,
                         cudaFuncAttributeMaxDynamicSharedMemorySize, SMEM3h);
    cudaFuncSetAttribute(k_p1_mma,
                         cudaFuncAttributeMaxDynamicSharedMemorySize, SMEM3h);
    cudaFuncSetAttribute(k_final_mma,
                         cudaFuncAttributeMaxDynamicSharedMemorySize, SMEM3h);

    k_repack<<<1372, 256>>>(offs_w, off0_w, conv_w, p1_w, g1_w, p2_w);
    k_nchw2nhwc<<<dim3(2048, BN), 256>>>(x);
    k_conv3x3_mma<<<dim3(16,32,BN), 256, SMEM3h>>>((float*)p_hraw);
    k_stats_final2<<<256, 64>>>();
    k_p1_mma<<<dim3(512, BN), 256, SMEM3h>>>(p1_b);
    k_conv_mma_h<50, 64, 25, 5, 1, 2><<<dim3(16,32,BN), 256, SMEM5h>>>(
        (const __half*)p_th, (const __half*)p_wT0h, off0_b, (float*)p_off0);
    k_deform5<<<dim3(4096, BN), 256>>>(dw0_w);
    k_conv_mma_h<98, 112, 49, 7, 3, 9><<<dim3(16,32,BN), 256, SMEM7h>>>(
        (const __half*)p_ah, (const __half*)p_wTh, offs_b, (float*)p_offs);
    k_deform7<<<dim3(4096, BN), 256>>>(dws_w);
    k_final_mma<<<dim3(512, BN), 256, SMEM3h>>>(g1_b, p2_b, out);
}